// round 9
// baseline (speedup 1.0000x reference)
#include <cuda_runtime.h>
#include <cuda_fp16.h>
#include <math.h>

#define NTHR 1024
#define NC 8            // cluster size (portable max -> guaranteed schedulable)

#define NB 2
#define NF 32
#define ND 512
#define NH 8
#define NHD 64
#define NFF 2048
#define NL 4
#define NM 256

// ---------------- persistent device state (no allocs) ----------------
__device__ __align__(16) float g_K [NL][NB][NF][ND];
__device__ __align__(16) float g_V [NL][NB][NF][ND];
__device__ __align__(16) float g_Vt[NL][NB][NF][ND];
__device__ __align__(16) float g_CA[NL][NB][NF][ND];
__device__ __align__(16) float g_gb[NL * 3][NB][2 * ND];
__device__ __align__(16) float g_ppe[NF][ND];
__device__ __align__(16) float g_x0[NB][ND];
__device__ __align__(16) float g_q [NB][ND];
__device__ __align__(16) float g_y1[NB][ND];
__device__ __align__(16) float g_x2[NB][ND];
__device__ __align__(16) float g_h [NB][NFF];
__device__ __align__(16) float g_y3[NB][ND];

// fp16 weight copies (converted in preamble; halves step-loop traffic)
__device__ __align__(16) __half hWq[NL * ND * ND];
__device__ __align__(16) __half hWk[NL * ND * ND];
__device__ __align__(16) __half hWv[NL * ND * ND];
__device__ __align__(16) __half hWo[NL * ND * ND];
__device__ __align__(16) __half hW1[NL * ND * NFF];
__device__ __align__(16) __half hW2[NL * NFF * ND];
__device__ __align__(16) __half hMo[NM * ND];
__device__ __align__(16) __half hMr[ND * NM];

struct __align__(16) Smem {
    float x[1024];      // generic dual-batch vector
    float h[4096];      // FF hidden dual-batch / 8-row x for precompute GEMM
    float part[8192];   // GEMV reduction scratch (32 warp-groups x 2*COLS)
    float o[1024];      // attention output dual-batch
    float att[512];     // softmax weights [b][h][j]
    float red[96];      // SALN reduction scratch
};
#define SMEM_BYTES sizeof(Smem)

// ---------------- HW cluster barrier ----------------
__device__ __forceinline__ void csync() {
    asm volatile("barrier.cluster.arrive.aligned;" ::: "memory");
    asm volatile("barrier.cluster.wait.aligned;" ::: "memory");
}

// ---------------- fp32 -> fp16 strided converter ----------------
__device__ __forceinline__ void cvt_half(__half* dst, const float* __restrict__ src,
                                         int n2, int gtid, int gstride) {
    const float2* s = reinterpret_cast<const float2*>(src);
    __half2* d = reinterpret_cast<__half2*>(dst);
    for (int i = gtid; i < n2; i += gstride)
        d[i] = __floats2half2_rn(s[i].x, s[i].y);
}

// ---------------- redundant dual-batch SALN over arr (1024) ---------------
// warps 0..15 handle batch0 (arr[0..511]), warps 16..31 batch1.
__device__ __forceinline__ void saln1024(float* arr, const float* G0, const float* G1,
                                         const float* add0, const float* add1,
                                         float* red) {
    int tid = threadIdx.x;
    int half = tid >> 9, t = tid & 511;
    const float* G = half ? G1 : G0;
    const float* ad = half ? add1 : add0;
    float a = arr[tid];
    float s = a, q = a * a;
#pragma unroll
    for (int o = 16; o; o >>= 1) {
        s += __shfl_xor_sync(0xffffffffu, s, o);
        q += __shfl_xor_sync(0xffffffffu, q, o);
    }
    int wid = tid >> 5;
    if ((tid & 31) == 0) { red[wid] = s; red[32 + wid] = q; }
    __syncthreads();
    if (tid < 2) {
        float S = 0.f, Q = 0.f;
#pragma unroll
        for (int k = 0; k < 16; k++) { S += red[tid * 16 + k]; Q += red[32 + tid * 16 + k]; }
        float mu = S * (1.f / 512.f);
        red[64 + tid] = mu;
        red[66 + tid] = rsqrtf(Q * (1.f / 512.f) - mu * mu + 1e-5f);
    }
    __syncthreads();
    float mu = red[64 + half], rs = red[66 + half];
    float o = (a - mu) * rs * G[t] + G[512 + t];
    if (ad) o += ad[t];
    __syncthreads();
    arr[tid] = o;
    __syncthreads();
}

// ---- fp16-weight dual-batch GEMV tile: COLS cols, packed f32x2 math -------
// W pre-offset to (row0, colbase), ldw in halves. Outputs valid for tid<COLS.
template <int COLS, int K>
__device__ __forceinline__ void dgemvh(const __half* __restrict__ W, int ldw,
                                       const float* __restrict__ x0,
                                       const float* __restrict__ x1,
                                       float* __restrict__ part,
                                       float& o0, float& o1) {
    const int QP = COLS / 8;            // 8-half quads per row
    const int G  = NTHR / QP;           // K-groups before butterfly
    const int KE = K / G;
    int tid = threadIdx.x;
    int tq = tid % QP, te = tid / QP;
    const __half* Wt = W + (size_t)(te * KE) * ldw + tq * 8;
    unsigned long long acc0[4] = {0ull, 0ull, 0ull, 0ull};
    unsigned long long acc1[4] = {0ull, 0ull, 0ull, 0ull};
#pragma unroll
    for (int e = 0; e < KE; e++) {
        float4 w4 = *reinterpret_cast<const float4*>(Wt + (size_t)e * ldw);
        const __half2* hw = reinterpret_cast<const __half2*>(&w4);
        float xa = x0[te * KE + e], xb = x1[te * KE + e];
        unsigned long long xa2, xb2;
        asm("mov.b64 %0, {%1, %1};" : "=l"(xa2) : "f"(xa));
        asm("mov.b64 %0, {%1, %1};" : "=l"(xb2) : "f"(xb));
#pragma unroll
        for (int q = 0; q < 4; q++) {
            float2 f = __half22float2(hw[q]);
            unsigned long long w2;
            asm("mov.b64 %0, {%1, %2};" : "=l"(w2) : "f"(f.x), "f"(f.y));
            asm("fma.rn.f32x2 %0, %1, %2, %0;" : "+l"(acc0[q]) : "l"(w2), "l"(xa2));
            asm("fma.rn.f32x2 %0, %1, %2, %0;" : "+l"(acc1[q]) : "l"(w2), "l"(xb2));
        }
    }
    // butterfly over te-values within each warp -> exactly 32 groups remain
#pragma unroll
    for (int ofs = QP; ofs < 32; ofs <<= 1) {
#pragma unroll
        for (int q = 0; q < 4; q++) {
            unsigned long long t0 = __shfl_xor_sync(0xffffffffu, acc0[q], ofs);
            unsigned long long t1 = __shfl_xor_sync(0xffffffffu, acc1[q], ofs);
            asm("add.rn.f32x2 %0, %0, %1;" : "+l"(acc0[q]) : "l"(t0));
            asm("add.rn.f32x2 %0, %0, %1;" : "+l"(acc1[q]) : "l"(t1));
        }
    }
    __syncthreads();                    // protect part reuse
    int w = tid >> 5;
    if ((tid & 31) < QP) {
#pragma unroll
        for (int q = 0; q < 4; q++) {
            float lo0, hi0, lo1, hi1;
            asm("mov.b64 {%0, %1}, %2;" : "=f"(lo0), "=f"(hi0) : "l"(acc0[q]));
            asm("mov.b64 {%0, %1}, %2;" : "=f"(lo1), "=f"(hi1) : "l"(acc1[q]));
            part[w * (2 * COLS) + tq * 8 + 2 * q    ] = lo0;
            part[w * (2 * COLS) + tq * 8 + 2 * q + 1] = hi0;
            part[w * (2 * COLS) + COLS + tq * 8 + 2 * q    ] = lo1;
            part[w * (2 * COLS) + COLS + tq * 8 + 2 * q + 1] = hi1;
        }
    }
    __syncthreads();
    o0 = 0.f; o1 = 0.f;
    if (tid < COLS) {
        float s0 = 0.f, s1 = 0.f;
#pragma unroll
        for (int k = 0; k < 32; k++) {
            s0 += part[k * (2 * COLS) + tid];
            s1 += part[k * (2 * COLS) + COLS + tid];
        }
        o0 = s0; o1 = s1;
    }
}

// ---- fp32 dual-batch 32-col GEMV (preamble only), 1024 threads ------------
template <int K>
__device__ __forceinline__ void dgemv32(const float* __restrict__ W, int ldw,
                                        const float* __restrict__ x0,
                                        const float* __restrict__ x1,
                                        float* __restrict__ part,
                                        float& o0, float& o1) {
    const int KE = K / 128;
    int tid = threadIdx.x;
    int tq = tid & 7, te = tid >> 3;    // te 0..127
    const float* Wt = W + (size_t)(te * KE) * ldw + tq * 4;
    float a0 = 0, a1 = 0, a2 = 0, a3 = 0, b0 = 0, b1 = 0, b2 = 0, b3 = 0;
#pragma unroll
    for (int e = 0; e < KE; e++) {
        float4 w = *reinterpret_cast<const float4*>(Wt + (size_t)e * ldw);
        float xa = x0[te * KE + e], xb = x1[te * KE + e];
        a0 += xa * w.x; a1 += xa * w.y; a2 += xa * w.z; a3 += xa * w.w;
        b0 += xb * w.x; b1 += xb * w.y; b2 += xb * w.z; b3 += xb * w.w;
    }
#pragma unroll
    for (int ofs = 8; ofs < 32; ofs <<= 1) {
        a0 += __shfl_xor_sync(0xffffffffu, a0, ofs);
        a1 += __shfl_xor_sync(0xffffffffu, a1, ofs);
        a2 += __shfl_xor_sync(0xffffffffu, a2, ofs);
        a3 += __shfl_xor_sync(0xffffffffu, a3, ofs);
        b0 += __shfl_xor_sync(0xffffffffu, b0, ofs);
        b1 += __shfl_xor_sync(0xffffffffu, b1, ofs);
        b2 += __shfl_xor_sync(0xffffffffu, b2, ofs);
        b3 += __shfl_xor_sync(0xffffffffu, b3, ofs);
    }
    __syncthreads();
    int w = tid >> 5;
    if ((tid & 31) < 8) {
        float* P = part + w * 64 + tq * 4;
        P[0] = a0; P[1] = a1; P[2] = a2; P[3] = a3;
        P[32] = b0; P[33] = b1; P[34] = b2; P[35] = b3;
    }
    __syncthreads();
    o0 = 0.f; o1 = 0.f;
    if (tid < 32) {
        float s0 = 0.f, s1 = 0.f;
#pragma unroll
        for (int k = 0; k < 32; k++) {
            s0 += part[k * 64 + tid];
            s1 += part[k * 64 + 32 + tid];
        }
        o0 = s0; o1 = s1;
    }
}

// ---- 8-row x 64-col GEMM tile, K=512 (preamble only), 1024 threads --------
__device__ __forceinline__ void gemm8x64_512(const float* __restrict__ W, int ldw,
                                             const float* __restrict__ xs,
                                             float* __restrict__ part,
                                             float* out2 /* [512] valid tid<512 */) {
    int tid = threadIdx.x;
    int col = tid & 63, kg = tid >> 6;  // 16 k-groups of 32
    const float* Wp = W + (size_t)(kg * 32) * ldw + col;
    float acc[8];
#pragma unroll
    for (int rr = 0; rr < 8; rr++) acc[rr] = 0.f;
#pragma unroll 8
    for (int e = 0; e < 32; e++) {
        float w = Wp[(size_t)e * ldw];
#pragma unroll
        for (int rr = 0; rr < 8; rr++) acc[rr] += xs[rr * 512 + kg * 32 + e] * w;
    }
    __syncthreads();
#pragma unroll
    for (int rr = 0; rr < 8; rr++) part[(kg * 8 + rr) * 64 + col] = acc[rr];
    __syncthreads();
    if (tid < 512) {
        int orr = tid >> 6, ocol = tid & 63;
        float s = 0.f;
#pragma unroll
        for (int k = 0; k < 16; k++) s += part[(k * 8 + orr) * 64 + ocol];
        out2[tid] = s;
    }
    __syncthreads();
}

// ---------------------------------------------------------------------------
__global__ void __launch_bounds__(NTHR, 1) __cluster_dims__(NC, 1, 1) mega(
    const float* __restrict__ content, const float* __restrict__ style,
    const float* __restrict__ init_st,
    const float* __restrict__ motion_W, const float* __restrict__ motion_b,
    const float* __restrict__ motionr_W, const float* __restrict__ motionr_b,
    const float* __restrict__ sa_Wq, const float* __restrict__ sa_bq,
    const float* __restrict__ sa_Wk, const float* __restrict__ sa_bk,
    const float* __restrict__ sa_Wv, const float* __restrict__ sa_bv,
    const float* __restrict__ sa_Wo, const float* __restrict__ sa_bo,
    const float* __restrict__ ca_Wv, const float* __restrict__ ca_bv,
    const float* __restrict__ ca_Wo, const float* __restrict__ ca_bo,
    const float* __restrict__ ff_W1, const float* __restrict__ ff_b1,
    const float* __restrict__ ff_W2, const float* __restrict__ ff_b2,
    const float* __restrict__ saln_W, const float* __restrict__ saln_b,
    float* __restrict__ outp)
{
    extern __shared__ __align__(16) char dynsm[];
    Smem& sm = *reinterpret_cast<Smem*>(dynsm);
    const int cta = blockIdx.x, tid = threadIdx.x;
    const int gtid = cta * NTHR + tid, gstride = NC * NTHR;

    // ================= P0: weight conversion + PPE + gb + Vt ================
    cvt_half(hWq, sa_Wq, NL * ND * ND / 2, gtid, gstride);
    cvt_half(hWk, sa_Wk, NL * ND * ND / 2, gtid, gstride);
    cvt_half(hWv, sa_Wv, NL * ND * ND / 2, gtid, gstride);
    cvt_half(hWo, sa_Wo, NL * ND * ND / 2, gtid, gstride);
    cvt_half(hW1, ff_W1, NL * ND * NFF / 2, gtid, gstride);
    cvt_half(hW2, ff_W2, NL * NFF * ND / 2, gtid, gstride);
    cvt_half(hMo, motion_W, NM * ND / 2, gtid, gstride);
    cvt_half(hMr, motionr_W, ND * NM / 2, gtid, gstride);

    for (int idx = gtid; idx < NF * ND; idx += gstride) {
        int f = idx >> 9, d = idx & 511;
        float divv = expf((float)(d & ~1) * (-9.210340371976184f / 512.0f));
        float a = (float)(f % 30) * divv;
        g_ppe[f][d] = (d & 1) ? cosf(a) : sinf(a);
    }
    for (int u = tid; u < 1024; u += NTHR) sm.x[u] = style[u];
    __syncthreads();
    for (int t = cta; t < 384; t += NC) {         // 12 ls * 32 coltiles of 32
        int ls = t >> 5, colbase = (t & 31) * 32;
        float o0, o1;
        dgemv32<512>(saln_W + (size_t)ls * 524288 + colbase, 1024,
                     sm.x, sm.x + 512, sm.part, o0, o1);
        if (tid < 32) {
            int col = colbase + tid;
            float bb = saln_b[ls * 1024 + col];
            g_gb[ls][0][col] = o0 + bb;
            g_gb[ls][1][col] = o1 + bb;
        }
        __syncthreads();
    }
    for (int t = cta; t < 256; t += NC) {         // Vt = content@Wv+bv
        int l = t >> 6, ct = (t >> 3) & 7, rg = t & 7;
        int colbase = ct * 64;
        __syncthreads();
        for (int u = tid; u < 4096; u += NTHR) sm.h[u] = content[(size_t)rg * 4096 + u];
        __syncthreads();
        gemm8x64_512(ca_Wv + (size_t)l * 262144 + colbase, 512, sm.h, sm.part, sm.o);
        if (tid < 512) {
            int row = rg * 8 + (tid >> 6);
            int col = colbase + (tid & 63);
            g_Vt[l][row >> 5][row & 31][col] = sm.o[tid] + ca_bv[l * 512 + col];
        }
    }
    csync();

    // ================= P1: CA = Vt@Wo+bo, emb0 ===============================
    for (int t = cta; t < 256; t += NC) {
        int l = t >> 6, ct = (t >> 3) & 7, rg = t & 7;
        int colbase = ct * 64;
        __syncthreads();
        const float* vt = &g_Vt[l][0][0][0];
        for (int u = tid; u < 4096; u += NTHR) sm.h[u] = vt[(size_t)rg * 4096 + u];
        __syncthreads();
        gemm8x64_512(ca_Wo + (size_t)l * 262144 + colbase, 512, sm.h, sm.part, sm.o);
        if (tid < 512) {
            int row = rg * 8 + (tid >> 6);
            int col = colbase + (tid & 63);
            g_CA[l][row >> 5][row & 31][col] = sm.o[tid] + ca_bo[l * 512 + col];
        }
    }
    __syncthreads();
    if (tid < 256) { sm.x[tid] = init_st[tid]; sm.x[512 + tid] = init_st[256 + tid]; }
    __syncthreads();
    for (int t = cta; t < 16; t += NC) {          // emb0 (fp32, once)
        int colbase = t * 32;
        float o0, o1;
        dgemv32<256>(motion_W + colbase, 512, sm.x, sm.x + 512, sm.part, o0, o1);
        if (tid < 32) {
            int col = colbase + tid;
            float ex = motion_b[col] + g_ppe[0][col];
            g_x0[0][col] = o0 + ex;
            g_x0[1][col] = o1 + ex;
        }
        __syncthreads();
    }
    csync();

    // ================= autoregressive decode =================================
    for (int i = 0; i < NF; i++) {
        for (int l = 0; l < NL; l++) {
            // ---- A: (redundant saln3 of prev layer) + q/k/v (3 tiles) ----
            if (l == 0) {
                for (int u = tid; u < 1024; u += NTHR) sm.x[u] = ((const float*)g_x0)[u];
                __syncthreads();
            } else {
                for (int u = tid; u < 1024; u += NTHR) sm.x[u] = ((const float*)g_y3)[u];
                __syncthreads();
                saln1024(sm.x, g_gb[(l - 1) * 3 + 2][0], g_gb[(l - 1) * 3 + 2][1],
                         0, 0, sm.red);
                if (cta == 0) ((float*)g_x0)[tid] = sm.x[tid];
            }
#pragma unroll
            for (int s = 0; s < 3; s++) {
                int t = cta * 3 + s;               // 24 tiles of 64 cols
                int m = t >> 3, ct = t & 7;
                const __half* W = (m == 0 ? hWq : m == 1 ? hWk : hWv)
                                + (size_t)l * 262144 + ct * 64;
                float o0, o1;
                dgemvh<64, 512>(W, 512, sm.x, sm.x + 512, sm.part, o0, o1);
                if (tid < 64) {
                    int col = ct * 64 + tid;
                    const float* bias = m == 0 ? sa_bq : m == 1 ? sa_bk : sa_bv;
                    float bb = bias[l * 512 + col];
                    o0 += bb; o1 += bb;
                    if (m == 0)      { g_q[0][col] = o0;       g_q[1][col] = o1; }
                    else if (m == 1) { g_K[l][0][i][col] = o0; g_K[l][1][i][col] = o1; }
                    else             { g_V[l][0][i][col] = o0; g_V[l][1][i][col] = o1; }
                }
            }
            csync();

            // ---- B: redundant scores+softmax+attn-sum, then y1 (1 tile) ----
            {
                for (int u = tid; u < 1024; u += NTHR) sm.x[u] = ((const float*)g_q)[u];
                __syncthreads();
                int wid = tid >> 5, lane = tid & 31;
                if (wid < 16) {
                    int b = wid >> 3, h = wid & 7;
                    float sc = -1e30f;
                    if (lane <= i) {
                        const float4* kp = reinterpret_cast<const float4*>(&g_K[l][b][lane][h * 64]);
                        const float4* qp = reinterpret_cast<const float4*>(&sm.x[b * 512 + h * 64]);
                        float d = 0.f;
#pragma unroll
                        for (int e = 0; e < 16; e++) {
                            float4 kk = kp[e], qq = qp[e];
                            d += qq.x * kk.x + qq.y * kk.y + qq.z * kk.z + qq.w * kk.w;
                        }
                        sc = d * 0.125f - exp2f(-(float)(h + 1)) * (float)((i - lane) / 30);
                    }
                    float mx = sc;
#pragma unroll
                    for (int o = 16; o; o >>= 1) mx = fmaxf(mx, __shfl_xor_sync(0xffffffffu, mx, o));
                    float ev = (lane <= i) ? expf(sc - mx) : 0.f;
                    float smm = ev;
#pragma unroll
                    for (int o = 16; o; o >>= 1) smm += __shfl_xor_sync(0xffffffffu, smm, o);
                    sm.att[b * 256 + h * 32 + lane] = ev / smm;
                }
                __syncthreads();
                if (tid < 256) {                  // o = att @ V
                    int bb = tid >> 7, quad = tid & 127;
                    int hh = quad >> 4;
                    float4 acc = make_float4(0.f, 0.f, 0.f, 0.f);
#pragma unroll 4
                    for (int j = 0; j <= i; j++) {
                        float a = sm.att[bb * 256 + hh * 32 + j];
                        float4 v = reinterpret_cast<const float4*>(&g_V[l][bb][j][0])[quad];
                        acc.x += a * v.x; acc.y += a * v.y;
                        acc.z += a * v.z; acc.w += a * v.w;
                    }
                    reinterpret_cast<float4*>(sm.o)[bb * 128 + quad] = acc;
                }
                __syncthreads();
                float o0, o1;
                dgemvh<64, 512>(hWo + (size_t)l * 262144 + cta * 64, 512,
                                sm.o, sm.o + 512, sm.part, o0, o1);
                if (tid < 64) {
                    int col = cta * 64 + tid;
                    float bb2 = sa_bo[l * 512 + col];
                    g_y1[0][col] = o0 + bb2 + g_x0[0][col];
                    g_y1[1][col] = o1 + bb2 + g_x0[1][col];
                }
            }
            csync();

            // ---- C: redundant saln1+CA+saln2, then FF1 (2 tiles of 128) ----
            {
                for (int u = tid; u < 1024; u += NTHR) sm.x[u] = ((const float*)g_y1)[u];
                __syncthreads();
                saln1024(sm.x, g_gb[l * 3 + 0][0], g_gb[l * 3 + 0][1],
                         &g_CA[l][0][i][0], &g_CA[l][1][i][0], sm.red);
                saln1024(sm.x, g_gb[l * 3 + 1][0], g_gb[l * 3 + 1][1], 0, 0, sm.red);
                if (cta == 0) ((float*)g_x2)[tid] = sm.x[tid];
#pragma unroll
                for (int s = 0; s < 2; s++) {
                    int colbase = (cta * 2 + s) * 128;     // 16 tiles of 128
                    float o0, o1;
                    dgemvh<128, 512>(hW1 + (size_t)l * 1048576 + colbase, 2048,
                                     sm.x, sm.x + 512, sm.part, o0, o1);
                    if (tid < 128) {
                        int col = colbase + tid;
                        float bb = ff_b1[l * 2048 + col];
                        g_h[0][col] = fmaxf(o0 + bb, 0.f);
                        g_h[1][col] = fmaxf(o1 + bb, 0.f);
                    }
                }
            }
            csync();

            // ---- D: FF2 (1 tile) -> y3 ----
            {
                for (int u = tid; u < 1024; u += NTHR)
                    reinterpret_cast<float4*>(sm.h)[u] =
                        reinterpret_cast<const float4*>(&g_h[0][0])[u];
                __syncthreads();
                float o0, o1;
                dgemvh<64, 2048>(hW2 + (size_t)l * 1048576 + cta * 64, 512,
                                 sm.h, sm.h + 2048, sm.part, o0, o1);
                if (tid < 64) {
                    int col = cta * 64 + tid;
                    float bb = ff_b2[l * 512 + col];
                    g_y3[0][col] = o0 + bb + g_x2[0][col];
                    g_y3[1][col] = o1 + bb + g_x2[1][col];
                }
            }
            csync();
        } // layers

        // ---- OUT: row i = saln3(y3) @ motionr_W + br (1 tile of 32) ----
        {
            for (int u = tid; u < 1024; u += NTHR) sm.x[u] = ((const float*)g_y3)[u];
            __syncthreads();
            saln1024(sm.x, g_gb[11][0], g_gb[11][1], 0, 0, sm.red);
            float o0, o1;
            dgemvh<32, 512>(hMr + cta * 32, 256, sm.x, sm.x + 512, sm.part, o0, o1);
            if (tid < 32) {
                int col = cta * 32 + tid;
                float bb = motionr_b[col];
                outp[(size_t)i * 256 + col] = o0 + bb;
                outp[8192 + (size_t)i * 256 + col] = o1 + bb;
            }
        }
        csync();

        // ---- EMB: x0 = out_row @ motion_W + bm + ppe[i+1] (1 tile of 64) ----
        if (i < NF - 1) {
            if (tid < 256) {
                sm.x[tid] = outp[(size_t)i * 256 + tid];
                sm.x[512 + tid] = outp[8192 + (size_t)i * 256 + tid];
            }
            __syncthreads();
            float o0, o1;
            dgemvh<64, 256>(hMo + cta * 64, 512, sm.x, sm.x + 512, sm.part, o0, o1);
            if (tid < 64) {
                int col = cta * 64 + tid;
                float ex = motion_b[col] + g_ppe[i + 1][col];
                g_x0[0][col] = o0 + ex;
                g_x0[1][col] = o1 + ex;
            }
            csync();
        }
    } // steps
}

// ---------------------------------------------------------------------------
extern "C" void kernel_launch(void* const* d_in, const int* in_sizes, int n_in,
                              void* d_out, int out_size) {
    cudaFuncSetAttribute(mega, cudaFuncAttributeMaxDynamicSharedMemorySize,
                         (int)SMEM_BYTES);
    mega<<<NC, NTHR, SMEM_BYTES>>>(
        (const float*)d_in[0],  (const float*)d_in[1],  (const float*)d_in[2],
        (const float*)d_in[3],  (const float*)d_in[4],  (const float*)d_in[5],
        (const float*)d_in[6],
        (const float*)d_in[7],  (const float*)d_in[8],  (const float*)d_in[9],
        (const float*)d_in[10], (const float*)d_in[11], (const float*)d_in[12],
        (const float*)d_in[13], (const float*)d_in[14],
        /* ca_Wq/bq/Wk/bk (15-18) unused: one-hot cross-attn softmax */
        (const float*)d_in[19], (const float*)d_in[20], (const float*)d_in[21],
        (const float*)d_in[22],
        (const float*)d_in[23], (const float*)d_in[24], (const float*)d_in[25],
        (const float*)d_in[26],
        (const float*)d_in[27], (const float*)d_in[28],
        (float*)d_out);
    (void)in_sizes; (void)n_in; (void)out_size;
}

// round 10
// speedup vs baseline: 1.1194x; 1.1194x over previous
#include <cuda_runtime.h>
#include <cuda_fp16.h>
#include <math.h>

#define NTHR 512
#define NC 8            // cluster size (portable max)

#define NB 2
#define NF 32
#define ND 512
#define NH 8
#define NHD 64
#define NFF 2048
#define NL 4
#define NM 256

// ---------------- persistent device state (no allocs) ----------------
__device__ __align__(16) float g_Vt[NL][NB][NF][ND];
__device__ __align__(16) float g_CA[NL][NB][NF][ND];
__device__ __align__(16) float g_gb[NL * 3][NB][2 * ND];
__device__ __align__(16) float g_ppe[NF][ND];
__device__ __align__(16) float g_x0[NB][ND];
__device__ __align__(16) float g_h [NB][NFF];
__device__ __align__(16) float g_y3[NB][ND];
__device__ __align__(16) float g_part[NC][NB][ND];
__device__ __align__(16) float g_bcomb[ND];

// fp16 weights (converted/packed in preamble)
__device__ __align__(16) __half hQKV[NL * NH * ND * 256];   // [l][h][row512][256: q|k|v|pad]
__device__ __align__(16) __half hWo[NL * ND * ND];
__device__ __align__(16) __half hW1[NL * ND * NFF];
__device__ __align__(16) __half hW2[NL * NFF * ND];
__device__ __align__(16) __half hMr[ND * NM];
__device__ __align__(16) __half hMcomb[ND * ND];            // motionr_W @ motion_W

struct __align__(16) Smem {
    float x[1024];        // dual-batch activation
    float h[4096];        // FF hidden dual-batch / precompute staging
    float part[8192];     // GEMV reduction scratch
    float o[128];         // attn out [2][64]
    float q[128];         // q [2][64]
    float att[64];        // softmax [2][32]
    float red[96];
    float K[NL][NB][NF][65];   // per-head K cache (this CTA's head)
    float V[NL][NB][NF][65];   // per-head V cache
};
#define SMEM_BYTES sizeof(Smem)

__device__ __forceinline__ void csync() {
    asm volatile("barrier.cluster.arrive.aligned;" ::: "memory");
    asm volatile("barrier.cluster.wait.aligned;" ::: "memory");
}

__device__ __forceinline__ void cvt_half(__half* dst, const float* __restrict__ src,
                                         int n2, int gtid, int gstride) {
    const float2* s = reinterpret_cast<const float2*>(src);
    __half2* d = reinterpret_cast<__half2*>(dst);
    for (int i = gtid; i < n2; i += gstride)
        d[i] = __floats2half2_rn(s[i].x, s[i].y);
}

// ---------------- dual-batch SALN over arr[1024], 512 threads --------------
__device__ __forceinline__ void saln512(float* arr, const float* G0, const float* G1,
                                        const float* add0, const float* add1,
                                        float* red) {
    int tid = threadIdx.x;
    int half = tid >> 8, t = tid & 255;
    const float* G = half ? G1 : G0;
    const float* ad = half ? add1 : add0;
    float a0 = arr[half * 512 + t], a1 = arr[half * 512 + t + 256];
    float s = a0 + a1, q = a0 * a0 + a1 * a1;
#pragma unroll
    for (int o = 16; o; o >>= 1) {
        s += __shfl_xor_sync(0xffffffffu, s, o);
        q += __shfl_xor_sync(0xffffffffu, q, o);
    }
    int wid = tid >> 5;
    if ((tid & 31) == 0) { red[wid] = s; red[16 + wid] = q; }
    __syncthreads();
    if (tid < 2) {
        float S = 0.f, Q = 0.f;
#pragma unroll
        for (int k = 0; k < 8; k++) { S += red[tid * 8 + k]; Q += red[16 + tid * 8 + k]; }
        float mu = S * (1.f / 512.f);
        red[32 + tid] = mu;
        red[34 + tid] = rsqrtf(Q * (1.f / 512.f) - mu * mu + 1e-5f);
    }
    __syncthreads();
    float mu = red[32 + half], rs = red[34 + half];
    float o0 = (a0 - mu) * rs * G[t] + G[512 + t];
    float o1 = (a1 - mu) * rs * G[t + 256] + G[512 + t + 256];
    if (ad) { o0 += ad[t]; o1 += ad[t + 256]; }
    __syncthreads();
    arr[half * 512 + t] = o0; arr[half * 512 + t + 256] = o1;
    __syncthreads();
}

// ---- fp16 dual-batch GEMV tile: COLS cols in one wave, packed f32x2 -------
// W pre-offset (row0, colbase), ldw in halves. Outputs valid for tid < COLS.
template <int COLS, int K>
__device__ __forceinline__ void dgemvh(const __half* __restrict__ W, int ldw,
                                       const float* __restrict__ x0,
                                       const float* __restrict__ x1,
                                       float* __restrict__ part,
                                       float& o0, float& o1) {
    const int QP  = COLS / 8;
    const int GRP = NTHR / QP;
    const int KE  = K / GRP;
    const int NG  = (QP >= 32) ? GRP : 16;   // stored reduction groups
    int tid = threadIdx.x;
    int tq = tid % QP, te = tid / QP;
    const __half* Wt = W + (size_t)(te * KE) * ldw + tq * 8;
    unsigned long long acc0[4] = {0ull,0ull,0ull,0ull};
    unsigned long long acc1[4] = {0ull,0ull,0ull,0ull};
#pragma unroll 8
    for (int e = 0; e < KE; e++) {
        float4 w4 = *reinterpret_cast<const float4*>(Wt + (size_t)e * ldw);
        const __half2* hw = reinterpret_cast<const __half2*>(&w4);
        float xa = x0[te * KE + e], xb = x1[te * KE + e];
        unsigned long long xa2, xb2;
        asm("mov.b64 %0, {%1, %1};" : "=l"(xa2) : "f"(xa));
        asm("mov.b64 %0, {%1, %1};" : "=l"(xb2) : "f"(xb));
#pragma unroll
        for (int q = 0; q < 4; q++) {
            float2 f = __half22float2(hw[q]);
            unsigned long long w2;
            asm("mov.b64 %0, {%1, %2};" : "=l"(w2) : "f"(f.x), "f"(f.y));
            asm("fma.rn.f32x2 %0, %1, %2, %0;" : "+l"(acc0[q]) : "l"(w2), "l"(xa2));
            asm("fma.rn.f32x2 %0, %1, %2, %0;" : "+l"(acc1[q]) : "l"(w2), "l"(xb2));
        }
    }
    if (QP < 32) {   // butterfly te-values within warp -> 16 warp groups
#pragma unroll
        for (int ofs = QP; ofs < 32; ofs <<= 1) {
#pragma unroll
            for (int q = 0; q < 4; q++) {
                unsigned long long t0 = __shfl_xor_sync(0xffffffffu, acc0[q], ofs);
                unsigned long long t1 = __shfl_xor_sync(0xffffffffu, acc1[q], ofs);
                asm("add.rn.f32x2 %0, %0, %1;" : "+l"(acc0[q]) : "l"(t0));
                asm("add.rn.f32x2 %0, %0, %1;" : "+l"(acc1[q]) : "l"(t1));
            }
        }
    }
    __syncthreads();                    // protect part reuse
    {
        int g = (QP >= 32) ? te : (tid >> 5);
        bool wr = (QP >= 32) ? true : ((tid & 31) < QP);
        if (wr) {
#pragma unroll
            for (int q = 0; q < 4; q++) {
                float lo0, hi0, lo1, hi1;
                asm("mov.b64 {%0, %1}, %2;" : "=f"(lo0), "=f"(hi0) : "l"(acc0[q]));
                asm("mov.b64 {%0, %1}, %2;" : "=f"(lo1), "=f"(hi1) : "l"(acc1[q]));
                part[g * (2 * COLS) + tq * 8 + 2 * q    ] = lo0;
                part[g * (2 * COLS) + tq * 8 + 2 * q + 1] = hi0;
                part[g * (2 * COLS) + COLS + tq * 8 + 2 * q    ] = lo1;
                part[g * (2 * COLS) + COLS + tq * 8 + 2 * q + 1] = hi1;
            }
        }
    }
    __syncthreads();
    o0 = 0.f; o1 = 0.f;
    if (tid < COLS) {
        float s0 = 0.f, s1 = 0.f;
#pragma unroll
        for (int k = 0; k < NG; k++) {
            s0 += part[k * (2 * COLS) + tid];
            s1 += part[k * (2 * COLS) + COLS + tid];
        }
        o0 = s0; o1 = s1;
    }
}

// ---- fp32 dual-batch 32-col GEMV (preamble only) --------------------------
template <int K>
__device__ __forceinline__ void dgemv32(const float* __restrict__ W, int ldw,
                                        const float* __restrict__ x0,
                                        const float* __restrict__ x1,
                                        float* __restrict__ part,
                                        float& o0, float& o1) {
    const int G = 64, KE = K / G;
    int tq = threadIdx.x & 7, te = threadIdx.x >> 3;
    const float* Wt = W + (size_t)(te * KE) * ldw + tq * 4;
    float a0 = 0, a1 = 0, a2 = 0, a3 = 0, b0 = 0, b1 = 0, b2 = 0, b3 = 0;
#pragma unroll 8
    for (int e = 0; e < KE; e++) {
        float4 w = *reinterpret_cast<const float4*>(Wt + (size_t)e * ldw);
        float xa = x0[te * KE + e], xb = x1[te * KE + e];
        a0 += xa * w.x; a1 += xa * w.y; a2 += xa * w.z; a3 += xa * w.w;
        b0 += xb * w.x; b1 += xb * w.y; b2 += xb * w.z; b3 += xb * w.w;
    }
    __syncthreads();
    float* P = part + te * 64 + tq * 4;
    P[0] = a0; P[1] = a1; P[2] = a2; P[3] = a3;
    P[32] = b0; P[33] = b1; P[34] = b2; P[35] = b3;
    __syncthreads();
    o0 = 0.f; o1 = 0.f;
    if (threadIdx.x < 32) {
        float s0 = 0.f, s1 = 0.f;
#pragma unroll
        for (int g = 0; g < 64; g++) {
            s0 += part[g * 64 + threadIdx.x];
            s1 += part[g * 64 + 32 + threadIdx.x];
        }
        o0 = s0; o1 = s1;
    }
}

// ---- 8-row x 64-col GEMM tile, K=512 (preamble only) ----------------------
__device__ __forceinline__ float gemm8x64_512(const float* __restrict__ W, int ldw,
                                              const float* __restrict__ xs,
                                              float* __restrict__ part) {
    int col = threadIdx.x & 63, kg = threadIdx.x >> 6;
    const float* Wp = W + (size_t)(kg * 64) * ldw + col;
    float acc[8];
#pragma unroll
    for (int rr = 0; rr < 8; rr++) acc[rr] = 0.f;
#pragma unroll 8
    for (int e = 0; e < 64; e++) {
        float w = Wp[(size_t)e * ldw];
#pragma unroll
        for (int rr = 0; rr < 8; rr++) acc[rr] += xs[rr * 512 + kg * 64 + e] * w;
    }
    __syncthreads();
#pragma unroll
    for (int rr = 0; rr < 8; rr++) part[(kg * 8 + rr) * 64 + col] = acc[rr];
    __syncthreads();
    int orr = threadIdx.x >> 6, ocol = threadIdx.x & 63;
    float s = 0.f;
#pragma unroll
    for (int k = 0; k < 8; k++) s += part[(k * 8 + orr) * 64 + ocol];
    return s;
}

// ---------------------------------------------------------------------------
__global__ void __launch_bounds__(NTHR, 1) __cluster_dims__(NC, 1, 1) mega(
    const float* __restrict__ content, const float* __restrict__ style,
    const float* __restrict__ init_st,
    const float* __restrict__ motion_W, const float* __restrict__ motion_b,
    const float* __restrict__ motionr_W, const float* __restrict__ motionr_b,
    const float* __restrict__ sa_Wq, const float* __restrict__ sa_bq,
    const float* __restrict__ sa_Wk, const float* __restrict__ sa_bk,
    const float* __restrict__ sa_Wv, const float* __restrict__ sa_bv,
    const float* __restrict__ sa_Wo, const float* __restrict__ sa_bo,
    const float* __restrict__ ca_Wv, const float* __restrict__ ca_bv,
    const float* __restrict__ ca_Wo, const float* __restrict__ ca_bo,
    const float* __restrict__ ff_W1, const float* __restrict__ ff_b1,
    const float* __restrict__ ff_W2, const float* __restrict__ ff_b2,
    const float* __restrict__ saln_W, const float* __restrict__ saln_b,
    float* __restrict__ outp)
{
    extern __shared__ __align__(16) char dynsm[];
    Smem& sm = *reinterpret_cast<Smem*>(dynsm);
    const int cta = blockIdx.x, tid = threadIdx.x;
    const int gtid = cta * NTHR + tid, gstride = NC * NTHR;

    // ================= P0: conversions, packing, PPE, Mcomb, gb, Vt =========
    cvt_half(hWo, sa_Wo, NL * ND * ND / 2, gtid, gstride);
    cvt_half(hW1, ff_W1, NL * ND * NFF / 2, gtid, gstride);
    cvt_half(hW2, ff_W2, NL * NFF * ND / 2, gtid, gstride);
    cvt_half(hMr, motionr_W, ND * NM / 2, gtid, gstride);
    // packed QKV: [l][h] block of 512 rows x 256 cols (q|k|v|zero)
    {
        __half2* d = reinterpret_cast<__half2*>(hQKV);
        const int TOT2 = NL * NH * ND * 128;
        for (int i2 = gtid; i2 < TOT2; i2 += gstride) {
            int idx = i2 * 2;
            int l = idx >> 20;                 // 1048576 per layer
            int rem = idx & 1048575;
            int h = rem >> 17;                 // 131072 per head
            int rr = rem & 131071;
            int row = rr >> 8, colp = rr & 255;
            float v0 = 0.f, v1 = 0.f;
            if (colp < 192) {
                int m = colp >> 6, j = colp & 63;
                const float* src = (m == 0 ? sa_Wq : m == 1 ? sa_Wk : sa_Wv);
                const float* p = src + (size_t)l * 262144 + (size_t)row * 512 + h * 64 + j;
                v0 = p[0]; v1 = p[1];
            }
            d[i2] = __floats2half2_rn(v0, v1);
        }
    }
    for (int idx = gtid; idx < NF * ND; idx += gstride) {
        int f = idx >> 9, d = idx & 511;
        float divv = expf((float)(d & ~1) * (-9.210340371976184f / 512.0f));
        float a = (float)(f % 30) * divv;
        g_ppe[f][d] = (d & 1) ? cosf(a) : sinf(a);
    }
    // Mcomb = motionr_W(512x256) @ motion_W(256x512); CTA c does cols c*64..
    {
        float* MoS = (float*)&sm.K[0][0][0][0];        // 256x64 staging
        for (int u = tid; u < 256 * 64; u += NTHR) {
            int e = u >> 6, jj = u & 63;
            MoS[u] = motion_W[(size_t)e * 512 + cta * 64 + jj];
        }
        __syncthreads();
        int jj = tid & 63, kt = tid >> 6;              // kt 0..7
        for (int m = 0; m < 64; m++) {
            int k = kt + m * 8;
            const float* mr = motionr_W + (size_t)k * 256;
            float acc = 0.f;
#pragma unroll 8
            for (int e = 0; e < 256; e++) acc += mr[e] * MoS[e * 64 + jj];
            hMcomb[(size_t)k * 512 + cta * 64 + jj] = __float2half(acc);
        }
        if (tid < 64) {
            float acc = 0.f;
            for (int e = 0; e < 256; e++) acc += motionr_b[e] * MoS[e * 64 + tid];
            g_bcomb[cta * 64 + tid] = acc + motion_b[cta * 64 + tid];
        }
        __syncthreads();
    }
    // SALN gamma/beta
    for (int u = tid; u < 1024; u += NTHR) sm.x[u] = style[u];
    __syncthreads();
    for (int t = cta; t < 384; t += NC) {
        int ls = t >> 5, colbase = (t & 31) * 32;
        float o0, o1;
        dgemv32<512>(saln_W + (size_t)ls * 524288 + colbase, 1024,
                     sm.x, sm.x + 512, sm.part, o0, o1);
        if (tid < 32) {
            int col = colbase + tid;
            float bb = saln_b[ls * 1024 + col];
            g_gb[ls][0][col] = o0 + bb;
            g_gb[ls][1][col] = o1 + bb;
        }
        __syncthreads();
    }
    // Vt = content @ ca_Wv + bv
    for (int t = cta; t < 256; t += NC) {
        int l = t >> 6, ct = (t >> 3) & 7, rg = t & 7;
        int colbase = ct * 64;
        __syncthreads();
        for (int u = tid; u < 4096; u += NTHR) sm.h[u] = content[(size_t)rg * 4096 + u];
        __syncthreads();
        float s = gemm8x64_512(ca_Wv + (size_t)l * 262144 + colbase, 512, sm.h, sm.part);
        int row = rg * 8 + (tid >> 6);
        int col = colbase + (tid & 63);
        g_Vt[l][row >> 5][row & 31][col] = s + ca_bv[l * 512 + col];
    }
    csync();

    // ================= P1: CA = Vt @ ca_Wo + bo, emb0 ========================
    for (int t = cta; t < 256; t += NC) {
        int l = t >> 6, ct = (t >> 3) & 7, rg = t & 7;
        int colbase = ct * 64;
        __syncthreads();
        const float* vt = &g_Vt[l][0][0][0];
        for (int u = tid; u < 4096; u += NTHR) sm.h[u] = vt[(size_t)rg * 4096 + u];
        __syncthreads();
        float s = gemm8x64_512(ca_Wo + (size_t)l * 262144 + colbase, 512, sm.h, sm.part);
        int row = rg * 8 + (tid >> 6);
        int col = colbase + (tid & 63);
        g_CA[l][row >> 5][row & 31][col] = s + ca_bo[l * 512 + col];
    }
    __syncthreads();
    if (tid < 256) { sm.x[tid] = init_st[tid]; sm.x[512 + tid] = init_st[256 + tid]; }
    __syncthreads();
    for (int t = cta; t < 16; t += NC) {          // emb0 (fp32, once)
        int colbase = t * 32;
        float o0, o1;
        dgemv32<256>(motion_W + colbase, 512, sm.x, sm.x + 512, sm.part, o0, o1);
        if (tid < 32) {
            int col = colbase + tid;
            float ex = motion_b[col] + g_ppe[0][col];
            g_x0[0][col] = o0 + ex;
            g_x0[1][col] = o1 + ex;
        }
        __syncthreads();
    }
    csync();

    // ================= autoregressive decode =================================
    for (int i = 0; i < NF; i++) {
        for (int l = 0; l < NL; l++) {
            // ---- stage A: x prep + packed QKV (head cta) + attention + o@Wo partial
            if (l == 0) {
                for (int u = tid; u < 1024; u += NTHR) sm.x[u] = ((const float*)g_x0)[u];
                __syncthreads();
            } else {
                for (int u = tid; u < 1024; u += NTHR) sm.x[u] = ((const float*)g_y3)[u];
                __syncthreads();
                saln512(sm.x, g_gb[(l - 1) * 3 + 2][0], g_gb[(l - 1) * 3 + 2][1],
                        0, 0, sm.red);
            }
            {
                float o0, o1;
                dgemvh<256, 512>(hQKV + ((size_t)l * NH + cta) * 131072, 256,
                                 sm.x, sm.x + 512, sm.part, o0, o1);
                if (tid < 192) {
                    int m = tid >> 6, j = tid & 63;
                    int col = cta * 64 + j;
                    const float* bias = (m == 0 ? sa_bq : m == 1 ? sa_bk : sa_bv);
                    float bb = bias[l * 512 + col];
                    o0 += bb; o1 += bb;
                    if (m == 0)      { sm.q[j] = o0;           sm.q[64 + j] = o1; }
                    else if (m == 1) { sm.K[l][0][i][j] = o0;  sm.K[l][1][i][j] = o1; }
                    else             { sm.V[l][0][i][j] = o0;  sm.V[l][1][i][j] = o1; }
                }
                __syncthreads();
                // scores + softmax: warp 0 -> b0, warp 1 -> b1 (head = cta)
                if (tid < 64) {
                    int b = tid >> 5, j = tid & 31;
                    float sc = -1e30f;
                    if (j <= i) {
                        const float* kp = &sm.K[l][b][j][0];
                        const float* qp = &sm.q[b * 64];
                        float d = 0.f;
#pragma unroll 16
                        for (int e = 0; e < 64; e++) d += qp[e] * kp[e];
                        sc = d * 0.125f - exp2f(-(float)(cta + 1)) * (float)((i - j) / 30);
                    }
                    float mx = sc;
#pragma unroll
                    for (int o = 16; o; o >>= 1) mx = fmaxf(mx, __shfl_xor_sync(0xffffffffu, mx, o));
                    float ev = (j <= i) ? expf(sc - mx) : 0.f;
                    float smm = ev;
#pragma unroll
                    for (int o = 16; o; o >>= 1) smm += __shfl_xor_sync(0xffffffffu, smm, o);
                    sm.att[b * 32 + j] = ev / smm;
                }
                __syncthreads();
                if (tid < 128) {                   // o[b][d] = sum_j att * V[j][d]
                    int b = tid >> 6, d = tid & 63;
                    float acc = 0.f;
                    for (int j = 0; j <= i; j++)
                        acc += sm.att[b * 32 + j] * sm.V[l][b][j][d];
                    sm.o[b * 64 + d] = acc;
                }
                __syncthreads();
                // partial y1 = o_head @ Wo[rows cta*64..], all 512 cols
                dgemvh<512, 64>(hWo + (size_t)l * 262144 + (size_t)(cta * 64) * 512, 512,
                                sm.o, sm.o + 64, sm.part, o0, o1);
                if (tid < 512) {
                    g_part[cta][0][tid] = o0;
                    g_part[cta][1][tid] = o1;
                }
            }
            csync();

            // ---- stage C: sum partials + residual + saln1+CA+saln2 + FF1 ----
            {
                float s0 = 0.f, s1 = 0.f;
#pragma unroll
                for (int k = 0; k < NC; k++) {
                    s0 += g_part[k][0][tid];
                    s1 += g_part[k][1][tid];
                }
                float bb = sa_bo[l * 512 + tid];
                float y0 = s0 + bb + sm.x[tid];
                float y1 = s1 + bb + sm.x[512 + tid];
                __syncthreads();
                sm.x[tid] = y0; sm.x[512 + tid] = y1;
                __syncthreads();
                saln512(sm.x, g_gb[l * 3 + 0][0], g_gb[l * 3 + 0][1],
                        &g_CA[l][0][i][0], &g_CA[l][1][i][0], sm.red);
                saln512(sm.x, g_gb[l * 3 + 1][0], g_gb[l * 3 + 1][1], 0, 0, sm.red);
#pragma unroll
                for (int s = 0; s < 2; s++) {
                    int colbase = (cta * 2 + s) * 128;
                    float o0, o1;
                    dgemvh<128, 512>(hW1 + (size_t)l * 1048576 + colbase, 2048,
                                     sm.x, sm.x + 512, sm.part, o0, o1);
                    if (tid < 128) {
                        int col = colbase + tid;
                        float b1f = ff_b1[l * 2048 + col];
                        g_h[0][col] = fmaxf(o0 + b1f, 0.f);
                        g_h[1][col] = fmaxf(o1 + b1f, 0.f);
                    }
                }
            }
            csync();

            // ---- stage D: FF2 + residual (x2 still in sm.x) ----
            {
                for (int u = tid; u < 1024; u += NTHR)
                    reinterpret_cast<float4*>(sm.h)[u] =
                        reinterpret_cast<const float4*>(&g_h[0][0])[u];
                __syncthreads();
                float o0, o1;
                dgemvh<64, 2048>(hW2 + (size_t)l * 1048576 + cta * 64, 512,
                                 sm.h, sm.h + 2048, sm.part, o0, o1);
                if (tid < 64) {
                    int col = cta * 64 + tid;
                    float bb = ff_b2[l * 512 + col];
                    g_y3[0][col] = o0 + bb + sm.x[col];
                    g_y3[1][col] = o1 + bb + sm.x[512 + col];
                }
            }
            csync();
        } // layers

        // ---- stage OUT': saln3(y3) -> output row AND next embedding ----
        {
            for (int u = tid; u < 1024; u += NTHR) sm.x[u] = ((const float*)g_y3)[u];
            __syncthreads();
            saln512(sm.x, g_gb[11][0], g_gb[11][1], 0, 0, sm.red);
            float o0, o1;
            dgemvh<32, 512>(hMr + cta * 32, 256, sm.x, sm.x + 512, sm.part, o0, o1);
            if (tid < 32) {
                int col = cta * 32 + tid;
                float bb = motionr_b[col];
                outp[(size_t)i * 256 + col] = o0 + bb;
                outp[8192 + (size_t)i * 256 + col] = o1 + bb;
            }
            if (i < NF - 1) {   // emb directly from xs via composed matrix
                dgemvh<64, 512>(hMcomb + cta * 64, 512, sm.x, sm.x + 512, sm.part, o0, o1);
                if (tid < 64) {
                    int col = cta * 64 + tid;
                    float ex = g_bcomb[col] + g_ppe[i + 1][col];
                    g_x0[0][col] = o0 + ex;
                    g_x0[1][col] = o1 + ex;
                }
            }
        }
        csync();
    } // steps
}

// ---------------------------------------------------------------------------
extern "C" void kernel_launch(void* const* d_in, const int* in_sizes, int n_in,
                              void* d_out, int out_size) {
    cudaFuncSetAttribute(mega, cudaFuncAttributeMaxDynamicSharedMemorySize,
                         (int)SMEM_BYTES);
    mega<<<NC, NTHR, SMEM_BYTES>>>(
        (const float*)d_in[0],  (const float*)d_in[1],  (const float*)d_in[2],
        (const float*)d_in[3],  (const float*)d_in[4],  (const float*)d_in[5],
        (const float*)d_in[6],
        (const float*)d_in[7],  (const float*)d_in[8],  (const float*)d_in[9],
        (const float*)d_in[10], (const float*)d_in[11], (const float*)d_in[12],
        (const float*)d_in[13], (const float*)d_in[14],
        /* ca_Wq/bq/Wk/bk (15-18) unused: one-hot cross-attn softmax */
        (const float*)d_in[19], (const float*)d_in[20], (const float*)d_in[21],
        (const float*)d_in[22],
        (const float*)d_in[23], (const float*)d_in[24], (const float*)d_in[25],
        (const float*)d_in[26],
        (const float*)d_in[27], (const float*)d_in[28],
        (float*)d_out);
    (void)in_sizes; (void)n_in; (void)out_size;
}

// round 12
// speedup vs baseline: 1.5250x; 1.3623x over previous
#include <cuda_runtime.h>
#include <cuda_fp16.h>
#include <math.h>

#define NTHR 512
#define NC 8            // cluster size (portable max)

#define NB 2
#define NF 32
#define ND 512
#define NH 8
#define NHD 64
#define NFF 2048
#define NL 4
#define NM 256

// ---------------- persistent device state (no allocs) ----------------
__device__ __align__(16) float g_Vt[NL][NB][NF][ND];
__device__ __align__(16) float g_CA[NL][NB][NF][ND];
__device__ __align__(16) float g_gb[NL * 3][NB][2 * ND];
__device__ __align__(16) float g_ppe[NF][ND];
__device__ __align__(16) float g_x0[NB][ND];
__device__ __align__(16) float g_h [NB][NFF];
__device__ __align__(16) float g_y3[NB][ND];
__device__ __align__(16) float g_part[NC][NB][ND];
__device__ __align__(16) float g_bcomb[ND];

// fp16 weights (written by prep kernels)
__device__ __align__(16) __half hQKV[NL * NH * ND * 256];   // [l][h][row512][q64|k64|v64|pad64]
__device__ __align__(16) __half hWo[NL * ND * ND];
__device__ __align__(16) __half hW1[NL * ND * NFF];
__device__ __align__(16) __half hW2[NL * NFF * ND];
__device__ __align__(16) __half hMr[ND * NM];
__device__ __align__(16) __half hMcomb[ND * ND];            // motionr_W @ motion_W

struct __align__(16) Smem {
    float x[1024];
    float h[4096];
    float part[8192];
    float o[128];
    float q[128];
    float att[64];
    float red[96];
    float K[NL][NB][NF][65];
    float V[NL][NB][NF][65];
};
#define SMEM_BYTES sizeof(Smem)

__device__ __forceinline__ void csync() {
    asm volatile("barrier.cluster.arrive.aligned;" ::: "memory");
    asm volatile("barrier.cluster.wait.aligned;" ::: "memory");
}

// ======================= PREP KERNELS (R1-style: plain loops) ==============

// fp16 conversions + packed QKV + PPE
__global__ __launch_bounds__(256) void k_cvt(
    const float* __restrict__ sa_Wq, const float* __restrict__ sa_Wk,
    const float* __restrict__ sa_Wv, const float* __restrict__ sa_Wo,
    const float* __restrict__ ff_W1, const float* __restrict__ ff_W2,
    const float* __restrict__ motionr_W)
{
    int gtid = blockIdx.x * 256 + threadIdx.x;
    int gstride = gridDim.x * 256;
    for (int i = gtid; i < NL * ND * ND; i += gstride)
        hWo[i] = __float2half(sa_Wo[i]);
    for (int i = gtid; i < NL * ND * NFF; i += gstride)
        hW1[i] = __float2half(ff_W1[i]);
    for (int i = gtid; i < NL * NFF * ND; i += gstride)
        hW2[i] = __float2half(ff_W2[i]);
    for (int i = gtid; i < ND * NM; i += gstride)
        hMr[i] = __float2half(motionr_W[i]);
    for (int idx = gtid; idx < NL * NH * ND * 256; idx += gstride) {
        int l = idx >> 20;
        int rem = idx & 1048575;
        int h = rem >> 17;
        int rr = rem & 131071;
        int row = rr >> 8, colp = rr & 255;
        float v = 0.f;
        if (colp < 192) {
            int m = colp >> 6, j = colp & 63;
            const float* src = (m == 0 ? sa_Wq : m == 1 ? sa_Wk : sa_Wv);
            v = src[(size_t)l * 262144 + (size_t)row * 512 + h * 64 + j];
        }
        hQKV[idx] = __float2half(v);
    }
    for (int idx = gtid; idx < NF * ND; idx += gstride) {
        int f = idx >> 9, d = idx & 511;
        float divv = expf((float)(d & ~1) * (-9.210340371976184f / 512.0f));
        float a = (float)(f % 30) * divv;
        g_ppe[f][d] = (d & 1) ? cosf(a) : sinf(a);
    }
}

// SALN gamma/beta (thread-per-output, as R1 which passed)
__global__ __launch_bounds__(256) void k_gb(const float* __restrict__ style,
                                            const float* __restrict__ W,
                                            const float* __restrict__ bias) {
    int idx = blockIdx.x * 256 + threadIdx.x;     // < 12*2*1024 = 24576
    int j  = idx & 1023;
    int t  = idx >> 10;
    int b  = t & 1;
    int ls = t >> 1;
    float acc = bias[ls * 1024 + j];
    const float* w = W + (size_t)ls * 524288 + j;
    const float* x = style + b * 512;
    for (int e = 0; e < 512; e++) acc += x[e] * w[(size_t)e * 1024];
    g_gb[ls][b][j] = acc;
}

// Vt = content @ ca_Wv + bv (thread-per-output, as R1)
__global__ __launch_bounds__(256) void k_ca1(const float* __restrict__ content,
                                             const float* __restrict__ Wv,
                                             const float* __restrict__ bv) {
    int idx = blockIdx.x * 256 + threadIdx.x;     // < 131072
    int col = idx & 511;
    int l = idx >> 15;
    float acc = bv[l * 512 + col];
    const float* x = content + (size_t)((idx >> 9) & 63) * 512;
    const float* w = Wv + (size_t)l * 262144 + col;
    for (int e = 0; e < 512; e++) acc += x[e] * w[(size_t)e * 512];
    ((float*)g_Vt)[idx] = acc;
}

// CA = Vt @ ca_Wo + bo
__global__ __launch_bounds__(256) void k_ca2(const float* __restrict__ Wo,
                                             const float* __restrict__ bo) {
    int idx = blockIdx.x * 256 + threadIdx.x;
    int col = idx & 511;
    int l = idx >> 15;
    float acc = bo[l * 512 + col];
    const float* x = ((const float*)g_Vt) + (size_t)(idx >> 9) * 512;
    const float* w = Wo + (size_t)l * 262144 + col;
    for (int e = 0; e < 512; e++) acc += x[e] * w[(size_t)e * 512];
    ((float*)g_CA)[idx] = acc;
}

// Mcomb = motionr_W @ motion_W (thread-per-output)
__global__ __launch_bounds__(256) void k_mcomb(const float* __restrict__ motionr_W,
                                               const float* __restrict__ motion_W) {
    int idx = blockIdx.x * 256 + threadIdx.x;     // < 262144
    int row = idx >> 9, col = idx & 511;
    const float* mr = motionr_W + (size_t)row * 256;
    float acc = 0.f;
    for (int e = 0; e < 256; e++) acc += mr[e] * motion_W[(size_t)e * 512 + col];
    hMcomb[idx] = __float2half(acc);
}

// bcomb + emb0 (thread-per-output)
__global__ __launch_bounds__(256) void k_tail(const float* __restrict__ motionr_b,
                                              const float* __restrict__ motion_W,
                                              const float* __restrict__ motion_b,
                                              const float* __restrict__ init_st) {
    int blk = blockIdx.x, tid = threadIdx.x;
    if (blk < 4) {                                 // emb0: 1024 outputs
        int idx = blk * 256 + tid;
        int b = idx >> 9, col = idx & 511;
        const float* x = init_st + b * 256;
        float acc = 0.f;
        for (int e = 0; e < 256; e++) acc += x[e] * motion_W[(size_t)e * 512 + col];
        g_x0[b][col] = acc + motion_b[col] + g_ppe[0][col];
    } else {                                       // bcomb: 512 outputs
        int col = (blk - 4) * 256 + tid;
        float acc = 0.f;
        for (int e = 0; e < 256; e++) acc += motionr_b[e] * motion_W[(size_t)e * 512 + col];
        g_bcomb[col] = acc + motion_b[col];
    }
}

// ======================= DECODE HELPERS (identical to R10) =================

__device__ __forceinline__ void saln512(float* arr, const float* G0, const float* G1,
                                        const float* add0, const float* add1,
                                        float* red) {
    int tid = threadIdx.x;
    int half = tid >> 8, t = tid & 255;
    const float* G = half ? G1 : G0;
    const float* ad = half ? add1 : add0;
    float a0 = arr[half * 512 + t], a1 = arr[half * 512 + t + 256];
    float s = a0 + a1, q = a0 * a0 + a1 * a1;
#pragma unroll
    for (int o = 16; o; o >>= 1) {
        s += __shfl_xor_sync(0xffffffffu, s, o);
        q += __shfl_xor_sync(0xffffffffu, q, o);
    }
    int wid = tid >> 5;
    if ((tid & 31) == 0) { red[wid] = s; red[16 + wid] = q; }
    __syncthreads();
    if (tid < 2) {
        float S = 0.f, Q = 0.f;
#pragma unroll
        for (int k = 0; k < 8; k++) { S += red[tid * 8 + k]; Q += red[16 + tid * 8 + k]; }
        float mu = S * (1.f / 512.f);
        red[32 + tid] = mu;
        red[34 + tid] = rsqrtf(Q * (1.f / 512.f) - mu * mu + 1e-5f);
    }
    __syncthreads();
    float mu = red[32 + half], rs = red[34 + half];
    float o0 = (a0 - mu) * rs * G[t] + G[512 + t];
    float o1 = (a1 - mu) * rs * G[t + 256] + G[512 + t + 256];
    if (ad) { o0 += ad[t]; o1 += ad[t + 256]; }
    __syncthreads();
    arr[half * 512 + t] = o0; arr[half * 512 + t + 256] = o1;
    __syncthreads();
}

template <int COLS, int K>
__device__ __forceinline__ void dgemvh(const __half* __restrict__ W, int ldw,
                                       const float* __restrict__ x0,
                                       const float* __restrict__ x1,
                                       float* __restrict__ part,
                                       float& o0, float& o1) {
    const int QP  = COLS / 8;
    const int GRP = NTHR / QP;
    const int KE  = K / GRP;
    const int NG  = (QP >= 32) ? GRP : 16;
    int tid = threadIdx.x;
    int tq = tid % QP, te = tid / QP;
    const __half* Wt = W + (size_t)(te * KE) * ldw + tq * 8;
    unsigned long long acc0[4] = {0ull,0ull,0ull,0ull};
    unsigned long long acc1[4] = {0ull,0ull,0ull,0ull};
#pragma unroll 8
    for (int e = 0; e < KE; e++) {
        float4 w4 = *reinterpret_cast<const float4*>(Wt + (size_t)e * ldw);
        const __half2* hw = reinterpret_cast<const __half2*>(&w4);
        float xa = x0[te * KE + e], xb = x1[te * KE + e];
        unsigned long long xa2, xb2;
        asm("mov.b64 %0, {%1, %1};" : "=l"(xa2) : "f"(xa));
        asm("mov.b64 %0, {%1, %1};" : "=l"(xb2) : "f"(xb));
#pragma unroll
        for (int q = 0; q < 4; q++) {
            float2 f = __half22float2(hw[q]);
            unsigned long long w2;
            asm("mov.b64 %0, {%1, %2};" : "=l"(w2) : "f"(f.x), "f"(f.y));
            asm("fma.rn.f32x2 %0, %1, %2, %0;" : "+l"(acc0[q]) : "l"(w2), "l"(xa2));
            asm("fma.rn.f32x2 %0, %1, %2, %0;" : "+l"(acc1[q]) : "l"(w2), "l"(xb2));
        }
    }
    if (QP < 32) {
#pragma unroll
        for (int ofs = QP; ofs < 32; ofs <<= 1) {
#pragma unroll
            for (int q = 0; q < 4; q++) {
                unsigned long long t0 = __shfl_xor_sync(0xffffffffu, acc0[q], ofs);
                unsigned long long t1 = __shfl_xor_sync(0xffffffffu, acc1[q], ofs);
                asm("add.rn.f32x2 %0, %0, %1;" : "+l"(acc0[q]) : "l"(t0));
                asm("add.rn.f32x2 %0, %0, %1;" : "+l"(acc1[q]) : "l"(t1));
            }
        }
    }
    __syncthreads();
    {
        int g = (QP >= 32) ? te : (tid >> 5);
        bool wr = (QP >= 32) ? true : ((tid & 31) < QP);
        if (wr) {
#pragma unroll
            for (int q = 0; q < 4; q++) {
                float lo0, hi0, lo1, hi1;
                asm("mov.b64 {%0, %1}, %2;" : "=f"(lo0), "=f"(hi0) : "l"(acc0[q]));
                asm("mov.b64 {%0, %1}, %2;" : "=f"(lo1), "=f"(hi1) : "l"(acc1[q]));
                part[g * (2 * COLS) + tq * 8 + 2 * q    ] = lo0;
                part[g * (2 * COLS) + tq * 8 + 2 * q + 1] = hi0;
                part[g * (2 * COLS) + COLS + tq * 8 + 2 * q    ] = lo1;
                part[g * (2 * COLS) + COLS + tq * 8 + 2 * q + 1] = hi1;
            }
        }
    }
    __syncthreads();
    o0 = 0.f; o1 = 0.f;
    if (tid < COLS) {
        float s0 = 0.f, s1 = 0.f;
#pragma unroll
        for (int k = 0; k < NG; k++) {
            s0 += part[k * (2 * COLS) + tid];
            s1 += part[k * (2 * COLS) + COLS + tid];
        }
        o0 = s0; o1 = s1;
    }
}

// ======================= DECODE MEGAKERNEL (R10 decode loop) ===============
__global__ void __launch_bounds__(NTHR, 1) __cluster_dims__(NC, 1, 1) mega(
    const float* __restrict__ sa_bq, const float* __restrict__ sa_bk,
    const float* __restrict__ sa_bv, const float* __restrict__ sa_bo,
    const float* __restrict__ ff_b1, const float* __restrict__ ff_b2,
    const float* __restrict__ motionr_b,
    float* __restrict__ outp)
{
    extern __shared__ __align__(16) char dynsm[];
    Smem& sm = *reinterpret_cast<Smem*>(dynsm);
    const int cta = blockIdx.x, tid = threadIdx.x;

    for (int i = 0; i < NF; i++) {
        for (int l = 0; l < NL; l++) {
            // ---- stage A: x prep + packed QKV + attention + o@Wo partial ----
            if (l == 0) {
                for (int u = tid; u < 1024; u += NTHR) sm.x[u] = ((const float*)g_x0)[u];
                __syncthreads();
            } else {
                for (int u = tid; u < 1024; u += NTHR) sm.x[u] = ((const float*)g_y3)[u];
                __syncthreads();
                saln512(sm.x, g_gb[(l - 1) * 3 + 2][0], g_gb[(l - 1) * 3 + 2][1],
                        0, 0, sm.red);
            }
            {
                float o0, o1;
                dgemvh<256, 512>(hQKV + ((size_t)l * NH + cta) * 131072, 256,
                                 sm.x, sm.x + 512, sm.part, o0, o1);
                if (tid < 192) {
                    int m = tid >> 6, j = tid & 63;
                    int col = cta * 64 + j;
                    const float* bias = (m == 0 ? sa_bq : m == 1 ? sa_bk : sa_bv);
                    float bb = bias[l * 512 + col];
                    o0 += bb; o1 += bb;
                    if (m == 0)      { sm.q[j] = o0;           sm.q[64 + j] = o1; }
                    else if (m == 1) { sm.K[l][0][i][j] = o0;  sm.K[l][1][i][j] = o1; }
                    else             { sm.V[l][0][i][j] = o0;  sm.V[l][1][i][j] = o1; }
                }
                __syncthreads();
                if (tid < 64) {
                    int b = tid >> 5, j = tid & 31;
                    float sc = -1e30f;
                    if (j <= i) {
                        const float* kp = &sm.K[l][b][j][0];
                        const float* qp = &sm.q[b * 64];
                        float d = 0.f;
#pragma unroll 16
                        for (int e = 0; e < 64; e++) d += qp[e] * kp[e];
                        sc = d * 0.125f - exp2f(-(float)(cta + 1)) * (float)((i - j) / 30);
                    }
                    float mx = sc;
#pragma unroll
                    for (int o = 16; o; o >>= 1) mx = fmaxf(mx, __shfl_xor_sync(0xffffffffu, mx, o));
                    float ev = (j <= i) ? expf(sc - mx) : 0.f;
                    float smm = ev;
#pragma unroll
                    for (int o = 16; o; o >>= 1) smm += __shfl_xor_sync(0xffffffffu, smm, o);
                    sm.att[b * 32 + j] = ev / smm;
                }
                __syncthreads();
                if (tid < 128) {
                    int b = tid >> 6, d = tid & 63;
                    float acc = 0.f;
                    for (int j = 0; j <= i; j++)
                        acc += sm.att[b * 32 + j] * sm.V[l][b][j][d];
                    sm.o[b * 64 + d] = acc;
                }
                __syncthreads();
                dgemvh<512, 64>(hWo + (size_t)l * 262144 + (size_t)(cta * 64) * 512, 512,
                                sm.o, sm.o + 64, sm.part, o0, o1);
                if (tid < 512) {
                    g_part[cta][0][tid] = o0;
                    g_part[cta][1][tid] = o1;
                }
            }
            csync();

            // ---- stage C: sum partials + residual + saln1+CA+saln2 + FF1 ----
            {
                float s0 = 0.f, s1 = 0.f;
#pragma unroll
                for (int k = 0; k < NC; k++) {
                    s0 += g_part[k][0][tid];
                    s1 += g_part[k][1][tid];
                }
                float bb = sa_bo[l * 512 + tid];
                float y0 = s0 + bb + sm.x[tid];
                float y1 = s1 + bb + sm.x[512 + tid];
                __syncthreads();
                sm.x[tid] = y0; sm.x[512 + tid] = y1;
                __syncthreads();
                saln512(sm.x, g_gb[l * 3 + 0][0], g_gb[l * 3 + 0][1],
                        &g_CA[l][0][i][0], &g_CA[l][1][i][0], sm.red);
                saln512(sm.x, g_gb[l * 3 + 1][0], g_gb[l * 3 + 1][1], 0, 0, sm.red);
#pragma unroll
                for (int s = 0; s < 2; s++) {
                    int colbase = (cta * 2 + s) * 128;
                    float o0, o1;
                    dgemvh<128, 512>(hW1 + (size_t)l * 1048576 + colbase, 2048,
                                     sm.x, sm.x + 512, sm.part, o0, o1);
                    if (tid < 128) {
                        int col = colbase + tid;
                        float b1f = ff_b1[l * 2048 + col];
                        g_h[0][col] = fmaxf(o0 + b1f, 0.f);
                        g_h[1][col] = fmaxf(o1 + b1f, 0.f);
                    }
                }
            }
            csync();

            // ---- stage D: FF2 + residual (x2 still in sm.x) ----
            {
                for (int u = tid; u < 1024; u += NTHR)
                    reinterpret_cast<float4*>(sm.h)[u] =
                        reinterpret_cast<const float4*>(&g_h[0][0])[u];
                __syncthreads();
                float o0, o1;
                dgemvh<64, 2048>(hW2 + (size_t)l * 1048576 + cta * 64, 512,
                                 sm.h, sm.h + 2048, sm.part, o0, o1);
                if (tid < 64) {
                    int col = cta * 64 + tid;
                    float bb = ff_b2[l * 512 + col];
                    g_y3[0][col] = o0 + bb + sm.x[col];
                    g_y3[1][col] = o1 + bb + sm.x[512 + col];
                }
            }
            csync();
        } // layers

        // ---- stage OUT': saln3(y3) -> output row AND next embedding ----
        {
            for (int u = tid; u < 1024; u += NTHR) sm.x[u] = ((const float*)g_y3)[u];
            __syncthreads();
            saln512(sm.x, g_gb[11][0], g_gb[11][1], 0, 0, sm.red);
            float o0, o1;
            dgemvh<32, 512>(hMr + cta * 32, 256, sm.x, sm.x + 512, sm.part, o0, o1);
            if (tid < 32) {
                int col = cta * 32 + tid;
                float bb = motionr_b[col];
                outp[(size_t)i * 256 + col] = o0 + bb;
                outp[8192 + (size_t)i * 256 + col] = o1 + bb;
            }
            if (i < NF - 1) {
                dgemvh<64, 512>(hMcomb + cta * 64, 512, sm.x, sm.x + 512, sm.part, o0, o1);
                if (tid < 64) {
                    int col = cta * 64 + tid;
                    float ex = g_bcomb[col] + g_ppe[i + 1][col];
                    g_x0[0][col] = o0 + ex;
                    g_x0[1][col] = o1 + ex;
                }
            }
        }
        csync();
    } // steps
}

// ---------------------------------------------------------------------------
extern "C" void kernel_launch(void* const* d_in, const int* in_sizes, int n_in,
                              void* d_out, int out_size) {
    const float* content   = (const float*)d_in[0];
    const float* style     = (const float*)d_in[1];
    const float* init_st   = (const float*)d_in[2];
    const float* motion_W  = (const float*)d_in[3];
    const float* motion_b  = (const float*)d_in[4];
    const float* motionr_W = (const float*)d_in[5];
    const float* motionr_b = (const float*)d_in[6];
    const float* sa_Wq = (const float*)d_in[7];
    const float* sa_bq = (const float*)d_in[8];
    const float* sa_Wk = (const float*)d_in[9];
    const float* sa_bk = (const float*)d_in[10];
    const float* sa_Wv = (const float*)d_in[11];
    const float* sa_bv = (const float*)d_in[12];
    const float* sa_Wo = (const float*)d_in[13];
    const float* sa_bo = (const float*)d_in[14];
    // 15-18 (ca_Wq/bq/Wk/bk) unused: one-hot cross-attn softmax
    const float* ca_Wv = (const float*)d_in[19];
    const float* ca_bv = (const float*)d_in[20];
    const float* ca_Wo = (const float*)d_in[21];
    const float* ca_bo = (const float*)d_in[22];
    const float* ff_W1 = (const float*)d_in[23];
    const float* ff_b1 = (const float*)d_in[24];
    const float* ff_W2 = (const float*)d_in[25];
    const float* ff_b2 = (const float*)d_in[26];
    const float* saln_W = (const float*)d_in[27];
    const float* saln_b = (const float*)d_in[28];
    float* outp = (float*)d_out;

    k_cvt<<<1024, 256>>>(sa_Wq, sa_Wk, sa_Wv, sa_Wo, ff_W1, ff_W2, motionr_W);
    k_gb<<<96, 256>>>(style, saln_W, saln_b);
    k_ca1<<<512, 256>>>(content, ca_Wv, ca_bv);
    k_ca2<<<512, 256>>>(ca_Wo, ca_bo);
    k_mcomb<<<1024, 256>>>(motionr_W, motion_W);
    k_tail<<<6, 256>>>(motionr_b, motion_W, motion_b, init_st);

    cudaFuncSetAttribute(mega, cudaFuncAttributeMaxDynamicSharedMemorySize,
                         (int)SMEM_BYTES);
    mega<<<NC, NTHR, SMEM_BYTES>>>(sa_bq, sa_bk, sa_bv, sa_bo,
                                   ff_b1, ff_b2, motionr_b, outp);
    (void)in_sizes; (void)n_in; (void)out_size;
}

// round 13
// speedup vs baseline: 1.6442x; 1.0782x over previous
#include <cuda_runtime.h>
#include <cuda_fp16.h>
#include <math.h>

#define NTHR 512
#define NC 8            // cluster size (portable max)

#define NB 2
#define NF 32
#define ND 512
#define NH 8
#define NHD 64
#define NFF 2048
#define NL 4
#define NM 256

// ---------------- persistent device state (no allocs) ----------------
__device__ __align__(16) float g_Vt[NL][NB][NF][ND];
__device__ __align__(16) float g_CA[NL][NB][NF][ND];
__device__ __align__(16) float g_gb[NL * 3][NB][2 * ND];
__device__ __align__(16) float g_ppe[NF][ND];
__device__ __align__(16) float g_x0[NB][ND];
__device__ __align__(16) float g_part [NC][NB][ND];   // attn o@Wo partials
__device__ __align__(16) float g_part2[NC][NB][ND];   // FF2 partials
__device__ __align__(16) float g_bcomb[ND];

// fp16 weights (written by prep kernels)
__device__ __align__(16) __half hQKV[NL * NH * ND * 256];   // [l][h][row512][q64|k64|v64|pad64]
__device__ __align__(16) __half hWo[NL * ND * ND];
__device__ __align__(16) __half hW1[NL * ND * NFF];
__device__ __align__(16) __half hW2[NL * NFF * ND];
__device__ __align__(16) __half hOut[NC][ND][128];          // [cta][row][Mr32|Mcomb64|pad32]

struct __align__(16) Smem {
    float x[1024];          // dual-batch activation (persists across csync)
    float h[512];           // FF hidden slice [2][256]
    float part[8192];       // dgemvh reduction scratch
    float o[128];
    float q[128];
    float att[64];
    float red[96];
    float K[NL][NB][NF][65];
    float V[NL][NB][NF][65];
};
#define SMEM_BYTES sizeof(Smem)

__device__ __forceinline__ void csync() {
    asm volatile("barrier.cluster.arrive.aligned;" ::: "memory");
    asm volatile("barrier.cluster.wait.aligned;" ::: "memory");
}

// ======================= PREP KERNELS (plain loops; no spill risk) =========

__global__ __launch_bounds__(256) void k_cvt(
    const float* __restrict__ sa_Wq, const float* __restrict__ sa_Wk,
    const float* __restrict__ sa_Wv, const float* __restrict__ sa_Wo,
    const float* __restrict__ ff_W1, const float* __restrict__ ff_W2)
{
    int gtid = blockIdx.x * 256 + threadIdx.x;
    int gstride = gridDim.x * 256;
    for (int i = gtid; i < NL * ND * ND; i += gstride)
        hWo[i] = __float2half(sa_Wo[i]);
    for (int i = gtid; i < NL * ND * NFF; i += gstride)
        hW1[i] = __float2half(ff_W1[i]);
    for (int i = gtid; i < NL * NFF * ND; i += gstride)
        hW2[i] = __float2half(ff_W2[i]);
    for (int idx = gtid; idx < NL * NH * ND * 256; idx += gstride) {
        int l = idx >> 20;
        int rem = idx & 1048575;
        int h = rem >> 17;
        int rr = rem & 131071;
        int row = rr >> 8, colp = rr & 255;
        float v = 0.f;
        if (colp < 192) {
            int m = colp >> 6, j = colp & 63;
            const float* src = (m == 0 ? sa_Wq : m == 1 ? sa_Wk : sa_Wv);
            v = src[(size_t)l * 262144 + (size_t)row * 512 + h * 64 + j];
        }
        hQKV[idx] = __float2half(v);
    }
    for (int idx = gtid; idx < NF * ND; idx += gstride) {
        int f = idx >> 9, d = idx & 511;
        float divv = expf((float)(d & ~1) * (-9.210340371976184f / 512.0f));
        float a = (float)(f % 30) * divv;
        g_ppe[f][d] = (d & 1) ? cosf(a) : sinf(a);
    }
}

// packed output matrix: Mr | Mcomb | 0 (thread-per-output)
__global__ __launch_bounds__(256) void k_opack(const float* __restrict__ motionr_W,
                                               const float* __restrict__ motion_W) {
    int idx = blockIdx.x * 256 + threadIdx.x;     // < NC*512*128 = 524288
    if (idx >= NC * ND * 128) return;
    int c = idx >> 16, row = (idx >> 7) & 511, j = idx & 127;
    float v = 0.f;
    if (j < 32) {
        v = motionr_W[(size_t)row * 256 + c * 32 + j];
    } else if (j < 96) {
        int col = c * 64 + (j - 32);
        const float* mr = motionr_W + (size_t)row * 256;
        float acc = 0.f;
        for (int e = 0; e < 256; e++) acc += mr[e] * motion_W[(size_t)e * 512 + col];
        v = acc;
    }
    hOut[c][row][j] = __float2half(v);
}

__global__ __launch_bounds__(256) void k_gb(const float* __restrict__ style,
                                            const float* __restrict__ W,
                                            const float* __restrict__ bias) {
    int idx = blockIdx.x * 256 + threadIdx.x;     // < 24576
    int j  = idx & 1023;
    int t  = idx >> 10;
    int b  = t & 1;
    int ls = t >> 1;
    float acc = bias[ls * 1024 + j];
    const float* w = W + (size_t)ls * 524288 + j;
    const float* x = style + b * 512;
    for (int e = 0; e < 512; e++) acc += x[e] * w[(size_t)e * 1024];
    g_gb[ls][b][j] = acc;
}

__global__ __launch_bounds__(256) void k_ca1(const float* __restrict__ content,
                                             const float* __restrict__ Wv,
                                             const float* __restrict__ bv) {
    int idx = blockIdx.x * 256 + threadIdx.x;     // < 131072
    int col = idx & 511;
    int l = idx >> 15;
    float acc = bv[l * 512 + col];
    const float* x = content + (size_t)((idx >> 9) & 63) * 512;
    const float* w = Wv + (size_t)l * 262144 + col;
    for (int e = 0; e < 512; e++) acc += x[e] * w[(size_t)e * 512];
    ((float*)g_Vt)[idx] = acc;
}

__global__ __launch_bounds__(256) void k_ca2(const float* __restrict__ Wo,
                                             const float* __restrict__ bo) {
    int idx = blockIdx.x * 256 + threadIdx.x;
    int col = idx & 511;
    int l = idx >> 15;
    float acc = bo[l * 512 + col];
    const float* x = ((const float*)g_Vt) + (size_t)(idx >> 9) * 512;
    const float* w = Wo + (size_t)l * 262144 + col;
    for (int e = 0; e < 512; e++) acc += x[e] * w[(size_t)e * 512];
    ((float*)g_CA)[idx] = acc;
}

__global__ __launch_bounds__(256) void k_tail(const float* __restrict__ motionr_b,
                                              const float* __restrict__ motion_W,
                                              const float* __restrict__ motion_b,
                                              const float* __restrict__ init_st) {
    int blk = blockIdx.x, tid = threadIdx.x;
    if (blk < 4) {                                 // emb0
        int idx = blk * 256 + tid;
        int b = idx >> 9, col = idx & 511;
        const float* x = init_st + b * 256;
        float acc = 0.f;
        for (int e = 0; e < 256; e++) acc += x[e] * motion_W[(size_t)e * 512 + col];
        g_x0[b][col] = acc + motion_b[col] + g_ppe[0][col];
    } else {                                       // bcomb
        int col = (blk - 4) * 256 + tid;
        float acc = 0.f;
        for (int e = 0; e < 256; e++) acc += motionr_b[e] * motion_W[(size_t)e * 512 + col];
        g_bcomb[col] = acc + motion_b[col];
    }
}

// ======================= DECODE HELPERS ====================================

__device__ __forceinline__ void saln512(float* arr, const float* G0, const float* G1,
                                        const float* add0, const float* add1,
                                        float* red) {
    int tid = threadIdx.x;
    int half = tid >> 8, t = tid & 255;
    const float* G = half ? G1 : G0;
    const float* ad = half ? add1 : add0;
    float a0 = arr[half * 512 + t], a1 = arr[half * 512 + t + 256];
    float s = a0 + a1, q = a0 * a0 + a1 * a1;
#pragma unroll
    for (int o = 16; o; o >>= 1) {
        s += __shfl_xor_sync(0xffffffffu, s, o);
        q += __shfl_xor_sync(0xffffffffu, q, o);
    }
    int wid = tid >> 5;
    if ((tid & 31) == 0) { red[wid] = s; red[16 + wid] = q; }
    __syncthreads();
    if (tid < 2) {
        float S = 0.f, Q = 0.f;
#pragma unroll
        for (int k = 0; k < 8; k++) { S += red[tid * 8 + k]; Q += red[16 + tid * 8 + k]; }
        float mu = S * (1.f / 512.f);
        red[32 + tid] = mu;
        red[34 + tid] = rsqrtf(Q * (1.f / 512.f) - mu * mu + 1e-5f);
    }
    __syncthreads();
    float mu = red[32 + half], rs = red[34 + half];
    float o0 = (a0 - mu) * rs * G[t] + G[512 + t];
    float o1 = (a1 - mu) * rs * G[t + 256] + G[512 + t + 256];
    if (ad) { o0 += ad[t]; o1 += ad[t + 256]; }
    __syncthreads();
    arr[half * 512 + t] = o0; arr[half * 512 + t + 256] = o1;
    __syncthreads();
}

template <int COLS, int K>
__device__ __forceinline__ void dgemvh(const __half* __restrict__ W, int ldw,
                                       const float* __restrict__ x0,
                                       const float* __restrict__ x1,
                                       float* __restrict__ part,
                                       float& o0, float& o1) {
    const int QP  = COLS / 8;
    const int GRP = NTHR / QP;
    const int KE  = K / GRP;
    const int NG  = (QP >= 32) ? GRP : 16;
    int tid = threadIdx.x;
    int tq = tid % QP, te = tid / QP;
    const __half* Wt = W + (size_t)(te * KE) * ldw + tq * 8;
    unsigned long long acc0[4] = {0ull,0ull,0ull,0ull};
    unsigned long long acc1[4] = {0ull,0ull,0ull,0ull};
#pragma unroll 8
    for (int e = 0; e < KE; e++) {
        float4 w4 = *reinterpret_cast<const float4*>(Wt + (size_t)e * ldw);
        const __half2* hw = reinterpret_cast<const __half2*>(&w4);
        float xa = x0[te * KE + e], xb = x1[te * KE + e];
        unsigned long long xa2, xb2;
        asm("mov.b64 %0, {%1, %1};" : "=l"(xa2) : "f"(xa));
        asm("mov.b64 %0, {%1, %1};" : "=l"(xb2) : "f"(xb));
#pragma unroll
        for (int q = 0; q < 4; q++) {
            float2 f = __half22float2(hw[q]);
            unsigned long long w2;
            asm("mov.b64 %0, {%1, %2};" : "=l"(w2) : "f"(f.x), "f"(f.y));
            asm("fma.rn.f32x2 %0, %1, %2, %0;" : "+l"(acc0[q]) : "l"(w2), "l"(xa2));
            asm("fma.rn.f32x2 %0, %1, %2, %0;" : "+l"(acc1[q]) : "l"(w2), "l"(xb2));
        }
    }
    if (QP < 32) {
#pragma unroll
        for (int ofs = QP; ofs < 32; ofs <<= 1) {
#pragma unroll
            for (int q = 0; q < 4; q++) {
                unsigned long long t0 = __shfl_xor_sync(0xffffffffu, acc0[q], ofs);
                unsigned long long t1 = __shfl_xor_sync(0xffffffffu, acc1[q], ofs);
                asm("add.rn.f32x2 %0, %0, %1;" : "+l"(acc0[q]) : "l"(t0));
                asm("add.rn.f32x2 %0, %0, %1;" : "+l"(acc1[q]) : "l"(t1));
            }
        }
    }
    __syncthreads();
    {
        int g = (QP >= 32) ? te : (tid >> 5);
        bool wr = (QP >= 32) ? true : ((tid & 31) < QP);
        if (wr) {
#pragma unroll
            for (int q = 0; q < 4; q++) {
                float lo0, hi0, lo1, hi1;
                asm("mov.b64 {%0, %1}, %2;" : "=f"(lo0), "=f"(hi0) : "l"(acc0[q]));
                asm("mov.b64 {%0, %1}, %2;" : "=f"(lo1), "=f"(hi1) : "l"(acc1[q]));
                part[g * (2 * COLS) + tq * 8 + 2 * q    ] = lo0;
                part[g * (2 * COLS) + tq * 8 + 2 * q + 1] = hi0;
                part[g * (2 * COLS) + COLS + tq * 8 + 2 * q    ] = lo1;
                part[g * (2 * COLS) + COLS + tq * 8 + 2 * q + 1] = hi1;
            }
        }
    }
    __syncthreads();
    o0 = 0.f; o1 = 0.f;
    if (tid < COLS) {
        float s0 = 0.f, s1 = 0.f;
#pragma unroll
        for (int k = 0; k < NG; k++) {
            s0 += part[k * (2 * COLS) + tid];
            s1 += part[k * (2 * COLS) + COLS + tid];
        }
        o0 = s0; o1 = s1;
    }
}

// ======================= DECODE MEGAKERNEL =================================
__global__ void __launch_bounds__(NTHR, 1) __cluster_dims__(NC, 1, 1) mega(
    const float* __restrict__ sa_bq, const float* __restrict__ sa_bk,
    const float* __restrict__ sa_bv, const float* __restrict__ sa_bo,
    const float* __restrict__ ff_b1, const float* __restrict__ ff_b2,
    const float* __restrict__ motionr_b,
    float* __restrict__ outp)
{
    extern __shared__ __align__(16) char dynsm[];
    Smem& sm = *reinterpret_cast<Smem*>(dynsm);
    const int cta = blockIdx.x, tid = threadIdx.x;

    for (int i = 0; i < NF; i++) {
        for (int l = 0; l < NL; l++) {
            // ==== stage A: (merge FF2 partials + saln3 | load x0) + QKV + attn
            if (l == 0) {
                for (int u = tid; u < 1024; u += NTHR) sm.x[u] = ((const float*)g_x0)[u];
                __syncthreads();
            } else {
                // y3 = sum FF2 partials + b2 + x2 (x2 live in sm.x)
                float s0 = 0.f, s1 = 0.f;
#pragma unroll
                for (int k = 0; k < NC; k++) {
                    s0 += g_part2[k][0][tid];
                    s1 += g_part2[k][1][tid];
                }
                float bb = ff_b2[(l - 1) * 512 + tid];
                float y0 = s0 + bb + sm.x[tid];
                float y1 = s1 + bb + sm.x[512 + tid];
                sm.x[tid] = y0; sm.x[512 + tid] = y1;
                __syncthreads();
                saln512(sm.x, g_gb[(l - 1) * 3 + 2][0], g_gb[(l - 1) * 3 + 2][1],
                        0, 0, sm.red);
            }
            {
                float o0, o1;
                dgemvh<256, 512>(hQKV + ((size_t)l * NH + cta) * 131072, 256,
                                 sm.x, sm.x + 512, sm.part, o0, o1);
                if (tid < 192) {
                    int m = tid >> 6, j = tid & 63;
                    int col = cta * 64 + j;
                    const float* bias = (m == 0 ? sa_bq : m == 1 ? sa_bk : sa_bv);
                    float bb = bias[l * 512 + col];
                    o0 += bb; o1 += bb;
                    if (m == 0)      { sm.q[j] = o0;           sm.q[64 + j] = o1; }
                    else if (m == 1) { sm.K[l][0][i][j] = o0;  sm.K[l][1][i][j] = o1; }
                    else             { sm.V[l][0][i][j] = o0;  sm.V[l][1][i][j] = o1; }
                }
                __syncthreads();
                if (tid < 64) {
                    int b = tid >> 5, j = tid & 31;
                    float sc = -1e30f;
                    if (j <= i) {
                        const float* kp = &sm.K[l][b][j][0];
                        const float* qp = &sm.q[b * 64];
                        float d = 0.f;
#pragma unroll 16
                        for (int e = 0; e < 64; e++) d += qp[e] * kp[e];
                        sc = d * 0.125f - exp2f(-(float)(cta + 1)) * (float)((i - j) / 30);
                    }
                    float mx = sc;
#pragma unroll
                    for (int o = 16; o; o >>= 1) mx = fmaxf(mx, __shfl_xor_sync(0xffffffffu, mx, o));
                    float ev = (j <= i) ? expf(sc - mx) : 0.f;
                    float smm = ev;
#pragma unroll
                    for (int o = 16; o; o >>= 1) smm += __shfl_xor_sync(0xffffffffu, smm, o);
                    sm.att[b * 32 + j] = ev / smm;
                }
                __syncthreads();
                if (tid < 128) {
                    int b = tid >> 6, d = tid & 63;
                    float acc = 0.f;
                    for (int j = 0; j <= i; j++)
                        acc += sm.att[b * 32 + j] * sm.V[l][b][j][d];
                    sm.o[b * 64 + d] = acc;
                }
                __syncthreads();
                dgemvh<512, 64>(hWo + (size_t)l * 262144 + (size_t)(cta * 64) * 512, 512,
                                sm.o, sm.o + 64, sm.part, o0, o1);
                if (tid < 512) {
                    g_part[cta][0][tid] = o0;
                    g_part[cta][1][tid] = o1;
                }
            }
            csync();

            // ==== stage B: merge attn + saln1+CA+saln2 + FF1 slice + FF2 partial
            {
                float s0 = 0.f, s1 = 0.f;
#pragma unroll
                for (int k = 0; k < NC; k++) {
                    s0 += g_part[k][0][tid];
                    s1 += g_part[k][1][tid];
                }
                float bb = sa_bo[l * 512 + tid];
                float y0 = s0 + bb + sm.x[tid];         // residual: x (post-saln3)
                float y1 = s1 + bb + sm.x[512 + tid];
                sm.x[tid] = y0; sm.x[512 + tid] = y1;
                __syncthreads();
                saln512(sm.x, g_gb[l * 3 + 0][0], g_gb[l * 3 + 0][1],
                        &g_CA[l][0][i][0], &g_CA[l][1][i][0], sm.red);
                saln512(sm.x, g_gb[l * 3 + 1][0], g_gb[l * 3 + 1][1], 0, 0, sm.red);
                // FF1: this CTA's 256 cols -> sm.h (local)
                float o0, o1;
                dgemvh<256, 512>(hW1 + (size_t)l * 1048576 + cta * 256, 2048,
                                 sm.x, sm.x + 512, sm.part, o0, o1);
                if (tid < 256) {
                    float b1f = ff_b1[l * 2048 + cta * 256 + tid];
                    sm.h[tid] = fmaxf(o0 + b1f, 0.f);
                    sm.h[256 + tid] = fmaxf(o1 + b1f, 0.f);
                }
                __syncthreads();
                // FF2 partial over this CTA's 256 rows of W2, all 512 cols
                dgemvh<512, 256>(hW2 + (size_t)l * 1048576 + (size_t)(cta * 256) * 512, 512,
                                 sm.h, sm.h + 256, sm.part, o0, o1);
                if (tid < 512) {
                    g_part2[cta][0][tid] = o0;
                    g_part2[cta][1][tid] = o1;
                }
            }
            csync();
        } // layers

        // ==== stage OUT: merge FF2 + saln3 -> out row + next embedding ====
        {
            float s0 = 0.f, s1 = 0.f;
#pragma unroll
            for (int k = 0; k < NC; k++) {
                s0 += g_part2[k][0][tid];
                s1 += g_part2[k][1][tid];
            }
            float bb = ff_b2[3 * 512 + tid];
            float y0 = s0 + bb + sm.x[tid];
            float y1 = s1 + bb + sm.x[512 + tid];
            sm.x[tid] = y0; sm.x[512 + tid] = y1;
            __syncthreads();
            saln512(sm.x, g_gb[11][0], g_gb[11][1], 0, 0, sm.red);
            float o0, o1;
            dgemvh<128, 512>(&hOut[cta][0][0], 128, sm.x, sm.x + 512, sm.part, o0, o1);
            if (tid < 32) {
                int col = cta * 32 + tid;
                float bb2 = motionr_b[col];
                outp[(size_t)i * 256 + col] = o0 + bb2;
                outp[8192 + (size_t)i * 256 + col] = o1 + bb2;
            } else if (tid < 96 && i < NF - 1) {
                int col = cta * 64 + (tid - 32);
                float ex = g_bcomb[col] + g_ppe[i + 1][col];
                g_x0[0][col] = o0 + ex;
                g_x0[1][col] = o1 + ex;
            }
        }
        csync();
    } // steps
}

// ---------------------------------------------------------------------------
extern "C" void kernel_launch(void* const* d_in, const int* in_sizes, int n_in,
                              void* d_out, int out_size) {
    const float* content   = (const float*)d_in[0];
    const float* style     = (const float*)d_in[1];
    const float* init_st   = (const float*)d_in[2];
    const float* motion_W  = (const float*)d_in[3];
    const float* motion_b  = (const float*)d_in[4];
    const float* motionr_W = (const float*)d_in[5];
    const float* motionr_b = (const float*)d_in[6];
    const float* sa_Wq = (const float*)d_in[7];
    const float* sa_bq = (const float*)d_in[8];
    const float* sa_Wk = (const float*)d_in[9];
    const float* sa_bk = (const float*)d_in[10];
    const float* sa_Wv = (const float*)d_in[11];
    const float* sa_bv = (const float*)d_in[12];
    const float* sa_Wo = (const float*)d_in[13];
    const float* sa_bo = (const float*)d_in[14];
    // 15-18 (ca_Wq/bq/Wk/bk) unused: one-hot cross-attn softmax
    const float* ca_Wv = (const float*)d_in[19];
    const float* ca_bv = (const float*)d_in[20];
    const float* ca_Wo = (const float*)d_in[21];
    const float* ca_bo = (const float*)d_in[22];
    const float* ff_W1 = (const float*)d_in[23];
    const float* ff_b1 = (const float*)d_in[24];
    const float* ff_W2 = (const float*)d_in[25];
    const float* ff_b2 = (const float*)d_in[26];
    const float* saln_W = (const float*)d_in[27];
    const float* saln_b = (const float*)d_in[28];
    float* outp = (float*)d_out;

    k_cvt<<<1024, 256>>>(sa_Wq, sa_Wk, sa_Wv, sa_Wo, ff_W1, ff_W2);
    k_opack<<<2048, 256>>>(motionr_W, motion_W);
    k_gb<<<96, 256>>>(style, saln_W, saln_b);
    k_ca1<<<512, 256>>>(content, ca_Wv, ca_bv);
    k_ca2<<<512, 256>>>(ca_Wo, ca_bo);
    k_tail<<<6, 256>>>(motionr_b, motion_W, motion_b, init_st);

    cudaFuncSetAttribute(mega, cudaFuncAttributeMaxDynamicSharedMemorySize,
                         (int)SMEM_BYTES);
    mega<<<NC, NTHR, SMEM_BYTES>>>(sa_bq, sa_bk, sa_bv, sa_bo,
                                   ff_b1, ff_b2, motionr_b, outp);
    (void)in_sizes; (void)n_in; (void)out_size;
}

// round 15
// speedup vs baseline: 1.7847x; 1.0854x over previous
#include <cuda_runtime.h>
#include <cuda_fp16.h>
#include <math.h>

#define NTHR 512
#define NC 8            // cluster size (portable max; cluster-16 is toxic on this stack)

#define NB 2
#define NF 32
#define ND 512
#define NH 8
#define NHD 64
#define NFF 2048
#define NL 4
#define NM 256

// ---------------- persistent device state (no allocs) ----------------
__device__ __align__(16) float g_Vt[NL][NB][NF][ND];
__device__ __align__(16) float g_CA[NL][NB][NF][ND];
__device__ __align__(16) float g_gb[NL * 3][NB][2 * ND];
__device__ __align__(16) float g_ppe[NF][ND];
__device__ __align__(16) float g_x0[NB][ND];
__device__ __align__(16) float g_part [NC][NB][ND];   // attn o@Wo partials
__device__ __align__(16) float g_part2[NC][NB][ND];   // FF2 partials
__device__ __align__(16) float g_bcomb[ND];

// fragment-ordered fp16 weights (A-fragments for mma.m16n8k16, row.col)
// layout: [...][tile m][kstep s][lane 0..31][8 halves]  (one uint4 per lane)
__device__ __align__(16) __half fQKV[NL * NH * 12 * 32 * 256];  // 192 cols, K=512
__device__ __align__(16) __half fWo [NL * NC * 32 * 4  * 256];  // 512 cols, K=64
__device__ __align__(16) __half fW1 [NL * NC * 16 * 32 * 256];  // 256 cols, K=512
__device__ __align__(16) __half fW2 [NL * NC * 32 * 16 * 256];  // 512 cols, K=256
__device__ __align__(16) __half fOut[NC * 6 * 32 * 256];        // 96 cols (Mr32|Mcomb64), K=512

struct __align__(16) Smem {
    float x[1024];            // dual-batch activation fp32 (persists across csync)
    float o[128];             // attn out [2][64] fp32
    float q[128];             // q [2][64] fp32
    float att[64];
    float red[96];
    __align__(16) __half xh[1024];   // x as fp16 [2][512]
    __align__(16) __half hh[512];    // FF hidden slice fp16 [2][256]
    __align__(16) __half oh[128];    // attn out fp16 [2][64]
    float K[NL][NB][NF][65];
    float V[NL][NB][NF][65];
};
#define SMEM_BYTES sizeof(Smem)

__device__ __forceinline__ void csync() {
    asm volatile("barrier.cluster.arrive.aligned;" ::: "memory");
    asm volatile("barrier.cluster.wait.aligned;" ::: "memory");
}

// Fragment element mapping (shared by prep writers and consumer):
//   lane: g = lane>>2, tg = lane&3
//   e (0..7): row-in-tile i = g + ((e>>1)&1)*8
//             k-in-step  kk = tg*2 + (e&1) + ((e>>2)&1)*8
//   A[m16][k16] with A[i][k] = W[kglobal][colglobal]  (out = W^T x)

// ======================= PREP KERNELS (plain loops; no spill) ==============

__global__ __launch_bounds__(256) void k_ppe() {
    int idx = blockIdx.x * 256 + threadIdx.x;     // < NF*ND
    int f = idx >> 9, d = idx & 511;
    float divv = expf((float)(d & ~1) * (-9.210340371976184f / 512.0f));
    float a = (float)(f % 30) * divv;
    g_ppe[f][d] = (d & 1) ? cosf(a) : sinf(a);
}

__global__ __launch_bounds__(256) void k_fragQKV(const float* __restrict__ Wq,
                                                 const float* __restrict__ Wk,
                                                 const float* __restrict__ Wv) {
    int idx = blockIdx.x * 256 + threadIdx.x;     // < 3145728
    int e = idx & 7, lane = (idx >> 3) & 31, s = (idx >> 8) & 31;
    int q = idx >> 13;
    int m = q % 12, p = q / 12;
    int h = p & 7, l = p >> 3;
    int g = lane >> 2, tg = lane & 3;
    int i = g + ((e >> 1) & 1) * 8;
    int kk = tg * 2 + (e & 1) + ((e >> 2) & 1) * 8;
    int col192 = m * 16 + i;
    int mtx = col192 >> 6;
    int cw = h * 64 + (col192 & 63);
    int k = s * 16 + kk;
    const float* src = (mtx == 0 ? Wq : mtx == 1 ? Wk : Wv);
    fQKV[idx] = __float2half(src[(size_t)l * 262144 + (size_t)k * 512 + cw]);
}

__global__ __launch_bounds__(256) void k_fragWo(const float* __restrict__ Wo) {
    int idx = blockIdx.x * 256 + threadIdx.x;     // < 1048576
    int e = idx & 7, lane = (idx >> 3) & 31, s = (idx >> 8) & 3;
    int m = (idx >> 10) & 31, cta = (idx >> 15) & 7, l = idx >> 18;
    int g = lane >> 2, tg = lane & 3;
    int i = g + ((e >> 1) & 1) * 8;
    int kk = tg * 2 + (e & 1) + ((e >> 2) & 1) * 8;
    int col = m * 16 + i;
    int k = cta * 64 + s * 16 + kk;
    fWo[idx] = __float2half(Wo[(size_t)l * 262144 + (size_t)k * 512 + col]);
}

__global__ __launch_bounds__(256) void k_fragW1(const float* __restrict__ W1) {
    int idx = blockIdx.x * 256 + threadIdx.x;     // < 4194304
    int e = idx & 7, lane = (idx >> 3) & 31, s = (idx >> 8) & 31;
    int m = (idx >> 13) & 15, cta = (idx >> 17) & 7, l = idx >> 20;
    int g = lane >> 2, tg = lane & 3;
    int i = g + ((e >> 1) & 1) * 8;
    int kk = tg * 2 + (e & 1) + ((e >> 2) & 1) * 8;
    int col = cta * 256 + m * 16 + i;
    int k = s * 16 + kk;
    fW1[idx] = __float2half(W1[(size_t)l * 1048576 + (size_t)k * 2048 + col]);
}

__global__ __launch_bounds__(256) void k_fragW2(const float* __restrict__ W2) {
    int idx = blockIdx.x * 256 + threadIdx.x;     // < 4194304
    int e = idx & 7, lane = (idx >> 3) & 31, s = (idx >> 8) & 15;
    int m = (idx >> 12) & 31, cta = (idx >> 17) & 7, l = idx >> 20;
    int g = lane >> 2, tg = lane & 3;
    int i = g + ((e >> 1) & 1) * 8;
    int kk = tg * 2 + (e & 1) + ((e >> 2) & 1) * 8;
    int col = m * 16 + i;
    int k = cta * 256 + s * 16 + kk;
    fW2[idx] = __float2half(W2[(size_t)l * 1048576 + (size_t)k * 512 + col]);
}

__global__ __launch_bounds__(256) void k_fragOut(const float* __restrict__ motionr_W,
                                                 const float* __restrict__ motion_W) {
    int idx = blockIdx.x * 256 + threadIdx.x;     // < 393216
    int e = idx & 7, lane = (idx >> 3) & 31, s = (idx >> 8) & 31;
    int q = idx >> 13;
    int m = q % 6, cta = q / 6;
    int g = lane >> 2, tg = lane & 3;
    int i = g + ((e >> 1) & 1) * 8;
    int kk = tg * 2 + (e & 1) + ((e >> 2) & 1) * 8;
    int j = m * 16 + i;
    int k = s * 16 + kk;
    float v;
    if (j < 32) {
        v = motionr_W[(size_t)k * 256 + cta * 32 + j];
    } else {
        int col = cta * 64 + (j - 32);
        const float* mr = motionr_W + (size_t)k * 256;
        float acc = 0.f;
        for (int t = 0; t < 256; t++) acc += mr[t] * motion_W[(size_t)t * 512 + col];
        v = acc;
    }
    fOut[idx] = __float2half(v);
}

__global__ __launch_bounds__(256) void k_gb(const float* __restrict__ style,
                                            const float* __restrict__ W,
                                            const float* __restrict__ bias) {
    int idx = blockIdx.x * 256 + threadIdx.x;     // < 24576
    int j  = idx & 1023;
    int t  = idx >> 10;
    int b  = t & 1;
    int ls = t >> 1;
    float acc = bias[ls * 1024 + j];
    const float* w = W + (size_t)ls * 524288 + j;
    const float* x = style + b * 512;
    for (int e = 0; e < 512; e++) acc += x[e] * w[(size_t)e * 1024];
    g_gb[ls][b][j] = acc;
}

__global__ __launch_bounds__(256) void k_ca1(const float* __restrict__ content,
                                             const float* __restrict__ Wv,
                                             const float* __restrict__ bv) {
    int idx = blockIdx.x * 256 + threadIdx.x;     // < 131072
    int col = idx & 511;
    int l = idx >> 15;
    float acc = bv[l * 512 + col];
    const float* x = content + (size_t)((idx >> 9) & 63) * 512;
    const float* w = Wv + (size_t)l * 262144 + col;
    for (int e = 0; e < 512; e++) acc += x[e] * w[(size_t)e * 512];
    ((float*)g_Vt)[idx] = acc;
}

__global__ __launch_bounds__(256) void k_ca2(const float* __restrict__ Wo,
                                             const float* __restrict__ bo) {
    int idx = blockIdx.x * 256 + threadIdx.x;
    int col = idx & 511;
    int l = idx >> 15;
    float acc = bo[l * 512 + col];
    const float* x = ((const float*)g_Vt) + (size_t)(idx >> 9) * 512;
    const float* w = Wo + (size_t)l * 262144 + col;
    for (int e = 0; e < 512; e++) acc += x[e] * w[(size_t)e * 512];
    ((float*)g_CA)[idx] = acc;
}

__global__ __launch_bounds__(256) void k_tail(const float* __restrict__ motionr_b,
                                              const float* __restrict__ motion_W,
                                              const float* __restrict__ motion_b,
                                              const float* __restrict__ init_st) {
    int blk = blockIdx.x, tid = threadIdx.x;
    if (blk < 4) {                                 // emb0
        int idx = blk * 256 + tid;
        int b = idx >> 9, col = idx & 511;
        const float* x = init_st + b * 256;
        float acc = 0.f;
        for (int e = 0; e < 256; e++) acc += x[e] * motion_W[(size_t)e * 512 + col];
        g_x0[b][col] = acc + motion_b[col] + g_ppe[0][col];
    } else {                                       // bcomb
        int col = (blk - 4) * 256 + tid;
        float acc = 0.f;
        for (int e = 0; e < 256; e++) acc += motionr_b[e] * motion_W[(size_t)e * 512 + col];
        g_bcomb[col] = acc + motion_b[col];
    }
}

// ======================= DECODE HELPERS ====================================

__device__ __forceinline__ void saln512(float* arr, const float* G0, const float* G1,
                                        const float* add0, const float* add1,
                                        float* red) {
    int tid = threadIdx.x;
    int half = tid >> 8, t = tid & 255;
    const float* G = half ? G1 : G0;
    const float* ad = half ? add1 : add0;
    float a0 = arr[half * 512 + t], a1 = arr[half * 512 + t + 256];
    float s = a0 + a1, q = a0 * a0 + a1 * a1;
#pragma unroll
    for (int o = 16; o; o >>= 1) {
        s += __shfl_xor_sync(0xffffffffu, s, o);
        q += __shfl_xor_sync(0xffffffffu, q, o);
    }
    int wid = tid >> 5;
    if ((tid & 31) == 0) { red[wid] = s; red[16 + wid] = q; }
    __syncthreads();
    if (tid < 2) {
        float S = 0.f, Q = 0.f;
#pragma unroll
        for (int k = 0; k < 8; k++) { S += red[tid * 8 + k]; Q += red[16 + tid * 8 + k]; }
        float mu = S * (1.f / 512.f);
        red[32 + tid] = mu;
        red[34 + tid] = rsqrtf(Q * (1.f / 512.f) - mu * mu + 1e-5f);
    }
    __syncthreads();
    float mu = red[32 + half], rs = red[34 + half];
    float o0 = (a0 - mu) * rs * G[t] + G[512 + t];
    float o1 = (a1 - mu) * rs * G[t + 256] + G[512 + t + 256];
    if (ad) { o0 += ad[t]; o1 += ad[t + 256]; }
    __syncthreads();
    arr[half * 512 + t] = o0; arr[half * 512 + t + 256] = o1;
    __syncthreads();
}

__device__ __forceinline__ void mma16816(float& c0, float& c1, float& c2, float& c3,
                                         const uint4& a, unsigned b0, unsigned b1) {
    asm volatile("mma.sync.aligned.m16n8k16.row.col.f32.f16.f16.f32 "
                 "{%0,%1,%2,%3}, {%4,%5,%6,%7}, {%8,%9}, {%0,%1,%2,%3};"
                 : "+f"(c0), "+f"(c1), "+f"(c2), "+f"(c3)
                 : "r"(a.x), "r"(a.y), "r"(a.z), "r"(a.w), "r"(b0), "r"(b1));
}

// One 16-col tile over KSTEPS k16 steps. frag points at tile base.
// xh[n*xstride + k] fp16 activations (n = batch, lanes g<2 supply B).
// Returns c[4]; valid results extracted by lanes with (lane&3)==0:
//   rows g, g+8 of the tile; c0/c1 = batch0/1 at row g; c2/c3 at row g+8.
template <int KSTEPS>
__device__ __forceinline__ void mma_tile(const __half* __restrict__ frag,
                                         const __half* __restrict__ xh, int xstride,
                                         float c[4]) {
    int lane = threadIdx.x & 31;
    int g = lane >> 2, tg = lane & 3;
    float d0 = 0, d1 = 0, d2 = 0, d3 = 0;
    float e0 = 0, e1 = 0, e2 = 0, e3 = 0;
    const uint4* fp = reinterpret_cast<const uint4*>(frag) + lane;
#pragma unroll
    for (int s = 0; s < KSTEPS; s++) {
        uint4 a = fp[s * 32];
        unsigned b0 = 0, b1 = 0;
        if (g < 2) {
            const __half* xb = xh + g * xstride + s * 16 + tg * 2;
            b0 = *reinterpret_cast<const unsigned*>(xb);
            b1 = *reinterpret_cast<const unsigned*>(xb + 8);
        }
        if (s & 1) mma16816(e0, e1, e2, e3, a, b0, b1);
        else       mma16816(d0, d1, d2, d3, a, b0, b1);
    }
    c[0] = d0 + e0; c[1] = d1 + e1; c[2] = d2 + e2; c[3] = d3 + e3;
}

// ======================= DECODE MEGAKERNEL =================================
__global__ void __launch_bounds__(NTHR, 1) __cluster_dims__(NC, 1, 1) mega(
    const float* __restrict__ sa_bq, const float* __restrict__ sa_bk,
    const float* __restrict__ sa_bv, const float* __restrict__ sa_bo,
    const float* __restrict__ ff_b1, const float* __restrict__ ff_b2,
    const float* __restrict__ motionr_b,
    float* __restrict__ outp)
{
    extern __shared__ __align__(16) char dynsm[];
    Smem& sm = *reinterpret_cast<Smem*>(dynsm);
    const int cta = blockIdx.x, tid = threadIdx.x;
    const int w = tid >> 5, lane = tid & 31;
    const int g = lane >> 2, tg = lane & 3;

    for (int i = 0; i < NF; i++) {
        for (int l = 0; l < NL; l++) {
            // ==== stage A: (merge FF2 + saln3 | load x0) + QKV + attn + Wo partial
            if (l == 0) {
                for (int u = tid; u < 1024; u += NTHR) sm.x[u] = ((const float*)g_x0)[u];
                __syncthreads();
            } else {
                float s0 = 0.f, s1 = 0.f;
#pragma unroll
                for (int k = 0; k < NC; k++) {
                    s0 += g_part2[k][0][tid];
                    s1 += g_part2[k][1][tid];
                }
                float bb = ff_b2[(l - 1) * 512 + tid];
                float y0 = s0 + bb + sm.x[tid];
                float y1 = s1 + bb + sm.x[512 + tid];
                sm.x[tid] = y0; sm.x[512 + tid] = y1;
                __syncthreads();
                saln512(sm.x, g_gb[(l - 1) * 3 + 2][0], g_gb[(l - 1) * 3 + 2][1],
                        0, 0, sm.red);
            }
            // x -> fp16
            sm.xh[tid] = __float2half(sm.x[tid]);
            sm.xh[512 + tid] = __float2half(sm.x[512 + tid]);
            __syncthreads();
            // QKV: 12 warps, 1 tile each, K=512
            if (w < 12) {
                float c[4];
                mma_tile<32>(fQKV + (((size_t)(l * NH + cta) * 12 + w) * 32) * 256,
                             sm.xh, 512, c);
                if (tg == 0) {
#pragma unroll
                    for (int r = 0; r < 2; r++) {
                        int col192 = w * 16 + g + r * 8;
                        float v0 = c[r * 2], v1 = c[r * 2 + 1];
                        int mtx = col192 >> 6, j = col192 & 63;
                        int colg = cta * 64 + j;
                        const float* bias = (mtx == 0 ? sa_bq : mtx == 1 ? sa_bk : sa_bv);
                        float bb = bias[l * 512 + colg];
                        v0 += bb; v1 += bb;
                        if (mtx == 0)      { sm.q[j] = v0;          sm.q[64 + j] = v1; }
                        else if (mtx == 1) { sm.K[l][0][i][j] = v0; sm.K[l][1][i][j] = v1; }
                        else               { sm.V[l][0][i][j] = v0; sm.V[l][1][i][j] = v1; }
                    }
                }
            }
            __syncthreads();
            // scores + softmax (dual batch)
            if (tid < 64) {
                int b = tid >> 5, j = tid & 31;
                float sc = -1e30f;
                if (j <= i) {
                    const float* kp = &sm.K[l][b][j][0];
                    const float* qp = &sm.q[b * 64];
                    float d = 0.f;
#pragma unroll 16
                    for (int e = 0; e < 64; e++) d += qp[e] * kp[e];
                    sc = d * 0.125f - exp2f(-(float)(cta + 1)) * (float)((i - j) / 30);
                }
                float mx = sc;
#pragma unroll
                for (int o = 16; o; o >>= 1) mx = fmaxf(mx, __shfl_xor_sync(0xffffffffu, mx, o));
                float ev = (j <= i) ? expf(sc - mx) : 0.f;
                float smm = ev;
#pragma unroll
                for (int o = 16; o; o >>= 1) smm += __shfl_xor_sync(0xffffffffu, smm, o);
                sm.att[b * 32 + j] = ev / smm;
            }
            __syncthreads();
            if (tid < 128) {
                int b = tid >> 6, d = tid & 63;
                float acc = 0.f;
                for (int j = 0; j <= i; j++)
                    acc += sm.att[b * 32 + j] * sm.V[l][b][j][d];
                sm.o[b * 64 + d] = acc;
                sm.oh[b * 64 + d] = __float2half(acc);
            }
            __syncthreads();
            // Wo partial: 16 warps x 2 tiles, K=64
            {
#pragma unroll
                for (int tt = 0; tt < 2; tt++) {
                    int m = w * 2 + tt;
                    float c[4];
                    mma_tile<4>(fWo + (((size_t)(l * NC + cta) * 32 + m) * 4) * 256,
                                sm.oh, 64, c);
                    if (tg == 0) {
#pragma unroll
                        for (int r = 0; r < 2; r++) {
                            int col = m * 16 + g + r * 8;
                            g_part[cta][0][col] = c[r * 2];
                            g_part[cta][1][col] = c[r * 2 + 1];
                        }
                    }
                }
            }
            csync();

            // ==== stage B: merge attn + saln1+CA+saln2 + FF1 + FF2 partial ====
            {
                float s0 = 0.f, s1 = 0.f;
#pragma unroll
                for (int k = 0; k < NC; k++) {
                    s0 += g_part[k][0][tid];
                    s1 += g_part[k][1][tid];
                }
                float bb = sa_bo[l * 512 + tid];
                float y0 = s0 + bb + sm.x[tid];
                float y1 = s1 + bb + sm.x[512 + tid];
                sm.x[tid] = y0; sm.x[512 + tid] = y1;
                __syncthreads();
                saln512(sm.x, g_gb[l * 3 + 0][0], g_gb[l * 3 + 0][1],
                        &g_CA[l][0][i][0], &g_CA[l][1][i][0], sm.red);
                saln512(sm.x, g_gb[l * 3 + 1][0], g_gb[l * 3 + 1][1], 0, 0, sm.red);
                sm.xh[tid] = __float2half(sm.x[tid]);
                sm.xh[512 + tid] = __float2half(sm.x[512 + tid]);
                __syncthreads();
                // FF1: 16 warps x 1 tile, K=512 -> hh (fp16, local)
                {
                    float c[4];
                    mma_tile<32>(fW1 + (((size_t)(l * NC + cta) * 16 + w) * 32) * 256,
                                 sm.xh, 512, c);
                    if (tg == 0) {
#pragma unroll
                        for (int r = 0; r < 2; r++) {
                            int col = w * 16 + g + r * 8;      // 0..255 local
                            float b1f = ff_b1[l * 2048 + cta * 256 + col];
                            sm.hh[col] = __float2half(fmaxf(c[r * 2] + b1f, 0.f));
                            sm.hh[256 + col] = __float2half(fmaxf(c[r * 2 + 1] + b1f, 0.f));
                        }
                    }
                }
                __syncthreads();
                // FF2 partial: 16 warps x 2 tiles, K=256
#pragma unroll
                for (int tt = 0; tt < 2; tt++) {
                    int m = w * 2 + tt;
                    float c[4];
                    mma_tile<16>(fW2 + (((size_t)(l * NC + cta) * 32 + m) * 16) * 256,
                                 sm.hh, 256, c);
                    if (tg == 0) {
#pragma unroll
                        for (int r = 0; r < 2; r++) {
                            int col = m * 16 + g + r * 8;
                            g_part2[cta][0][col] = c[r * 2];
                            g_part2[cta][1][col] = c[r * 2 + 1];
                        }
                    }
                }
            }
            csync();
        } // layers

        // ==== stage OUT: merge FF2 + saln3 -> out row + next embedding ====
        {
            float s0 = 0.f, s1 = 0.f;
#pragma unroll
            for (int k = 0; k < NC; k++) {
                s0 += g_part2[k][0][tid];
                s1 += g_part2[k][1][tid];
            }
            float bb = ff_b2[3 * 512 + tid];
            float y0 = s0 + bb + sm.x[tid];
            float y1 = s1 + bb + sm.x[512 + tid];
            sm.x[tid] = y0; sm.x[512 + tid] = y1;
            __syncthreads();
            saln512(sm.x, g_gb[11][0], g_gb[11][1], 0, 0, sm.red);
            sm.xh[tid] = __float2half(sm.x[tid]);
            sm.xh[512 + tid] = __float2half(sm.x[512 + tid]);
            __syncthreads();
            if (w < 6) {
                float c[4];
                mma_tile<32>(fOut + (((size_t)(cta * 6 + w)) * 32) * 256,
                             sm.xh, 512, c);
                if (tg == 0) {
#pragma unroll
                    for (int r = 0; r < 2; r++) {
                        int j = w * 16 + g + r * 8;
                        float v0 = c[r * 2], v1 = c[r * 2 + 1];
                        if (j < 32) {
                            int col = cta * 32 + j;
                            float bb2 = motionr_b[col];
                            outp[(size_t)i * 256 + col] = v0 + bb2;
                            outp[8192 + (size_t)i * 256 + col] = v1 + bb2;
                        } else if (i < NF - 1) {
                            int col = cta * 64 + (j - 32);
                            float ex = g_bcomb[col] + g_ppe[i + 1][col];
                            g_x0[0][col] = v0 + ex;
                            g_x0[1][col] = v1 + ex;
                        }
                    }
                }
            }
        }
        csync();
    } // steps
}

// ---------------------------------------------------------------------------
extern "C" void kernel_launch(void* const* d_in, const int* in_sizes, int n_in,
                              void* d_out, int out_size) {
    const float* content   = (const float*)d_in[0];
    const float* style     = (const float*)d_in[1];
    const float* init_st   = (const float*)d_in[2];
    const float* motion_W  = (const float*)d_in[3];
    const float* motion_b  = (const float*)d_in[4];
    const float* motionr_W = (const float*)d_in[5];
    const float* motionr_b = (const float*)d_in[6];
    const float* sa_Wq = (const float*)d_in[7];
    const float* sa_bq = (const float*)d_in[8];
    const float* sa_Wk = (const float*)d_in[9];
    const float* sa_bk = (const float*)d_in[10];
    const float* sa_Wv = (const float*)d_in[11];
    const float* sa_bv = (const float*)d_in[12];
    const float* sa_Wo = (const float*)d_in[13];
    const float* sa_bo = (const float*)d_in[14];
    // 15-18 (ca_Wq/bq/Wk/bk) unused: one-hot cross-attn softmax
    const float* ca_Wv = (const float*)d_in[19];
    const float* ca_bv = (const float*)d_in[20];
    const float* ca_Wo = (const float*)d_in[21];
    const float* ca_bo = (const float*)d_in[22];
    const float* ff_W1 = (const float*)d_in[23];
    const float* ff_b1 = (const float*)d_in[24];
    const float* ff_W2 = (const float*)d_in[25];
    const float* ff_b2 = (const float*)d_in[26];
    const float* saln_W = (const float*)d_in[27];
    const float* saln_b = (const float*)d_in[28];
    float* outp = (float*)d_out;

    k_ppe<<<(NF * ND) / 256, 256>>>();
    k_fragQKV<<<3145728 / 256, 256>>>(sa_Wq, sa_Wk, sa_Wv);
    k_fragWo<<<1048576 / 256, 256>>>(sa_Wo);
    k_fragW1<<<4194304 / 256, 256>>>(ff_W1);
    k_fragW2<<<4194304 / 256, 256>>>(ff_W2);
    k_fragOut<<<393216 / 256, 256>>>(motionr_W, motion_W);
    k_gb<<<96, 256>>>(style, saln_W, saln_b);
    k_ca1<<<512, 256>>>(content, ca_Wv, ca_bv);
    k_ca2<<<512, 256>>>(ca_Wo, ca_bo);
    k_tail<<<6, 256>>>(motionr_b, motion_W, motion_b, init_st);

    cudaFuncSetAttribute(mega, cudaFuncAttributeMaxDynamicSharedMemorySize,
                         (int)SMEM_BYTES);
    mega<<<NC, NTHR, SMEM_BYTES>>>(sa_bq, sa_bk, sa_bv, sa_bo,
                                   ff_b1, ff_b2, motionr_b, outp);
    (void)in_sizes; (void)n_in; (void)out_size;
}

// round 16
// speedup vs baseline: 2.0031x; 1.1224x over previous
#include <cuda_runtime.h>
#include <cuda_fp16.h>
#include <math.h>

#define NTHR 512
#define NC 8            // cluster size (portable max); 2 clusters = 2 batches

#define NB 2
#define NF 32
#define ND 512
#define NH 8
#define NHD 64
#define NFF 2048
#define NL 4
#define NM 256

// ---------------- persistent device state (no allocs) ----------------
__device__ __align__(16) float g_Vt[NL][NB][NF][ND];
__device__ __align__(16) float g_CA[NL][NB][NF][ND];
__device__ __align__(16) float g_gb[NL * 3][NB][2 * ND];
__device__ __align__(16) float g_ppe[NF][ND];
__device__ __align__(16) float g_x0[NB][ND];
__device__ __align__(16) float g_part [NB][NC][ND];   // attn o@Wo partials
__device__ __align__(16) float g_part2[NB][NC][ND];   // FF2 partials
__device__ __align__(16) float g_bcomb[ND];

// fragment-ordered fp16 weights (A-fragments for mma.m16n8k16, row.col)
// layout: [...][tile m][kstep s][lane 0..31][8 halves]  (one uint4 per lane)
__device__ __align__(16) __half fQKV[NL * NH * 12 * 32 * 256];  // 192 cols, K=512
__device__ __align__(16) __half fWo [NL * NC * 32 * 4  * 256];  // 512 cols, K=64
__device__ __align__(16) __half fW1 [NL * NC * 16 * 32 * 256];  // 256 cols, K=512
__device__ __align__(16) __half fW2 [NL * NC * 32 * 16 * 256];  // 512 cols, K=256
__device__ __align__(16) __half fOut[NC * 6 * 32 * 256];        // 96 cols (Mr32|Mcomb64), K=512

struct __align__(16) Smem {
    float x[512];             // single-batch activation (persists across csync)
    float o[64];
    float q[64];
    float att[32];
    float red[64];
    __align__(16) __half xh[512];
    __align__(16) __half hh[256];
    __align__(16) __half oh[64];
    float K[NL][NF][65];      // this CTA's head, this cluster's batch
    float V[NL][NF][65];
};
#define SMEM_BYTES sizeof(Smem)

__device__ __forceinline__ void csync() {
    asm volatile("barrier.cluster.arrive.aligned;" ::: "memory");
    asm volatile("barrier.cluster.wait.aligned;" ::: "memory");
}

// Fragment element mapping (shared by prep writers and consumer):
//   lane: g = lane>>2, tg = lane&3
//   e (0..7): row-in-tile i = g + ((e>>1)&1)*8
//             k-in-step  kk = tg*2 + (e&1) + ((e>>2)&1)*8

// ======================= PREP KERNELS (plain loops; no spill) ==============

__global__ __launch_bounds__(256) void k_ppe() {
    int idx = blockIdx.x * 256 + threadIdx.x;
    int f = idx >> 9, d = idx & 511;
    float divv = expf((float)(d & ~1) * (-9.210340371976184f / 512.0f));
    float a = (float)(f % 30) * divv;
    g_ppe[f][d] = (d & 1) ? cosf(a) : sinf(a);
}

__global__ __launch_bounds__(256) void k_fragQKV(const float* __restrict__ Wq,
                                                 const float* __restrict__ Wk,
                                                 const float* __restrict__ Wv) {
    int idx = blockIdx.x * 256 + threadIdx.x;     // < 3145728
    int e = idx & 7, lane = (idx >> 3) & 31, s = (idx >> 8) & 31;
    int q = idx >> 13;
    int m = q % 12, p = q / 12;
    int h = p & 7, l = p >> 3;
    int g = lane >> 2, tg = lane & 3;
    int i = g + ((e >> 1) & 1) * 8;
    int kk = tg * 2 + (e & 1) + ((e >> 2) & 1) * 8;
    int col192 = m * 16 + i;
    int mtx = col192 >> 6;
    int cw = h * 64 + (col192 & 63);
    int k = s * 16 + kk;
    const float* src = (mtx == 0 ? Wq : mtx == 1 ? Wk : Wv);
    fQKV[idx] = __float2half(src[(size_t)l * 262144 + (size_t)k * 512 + cw]);
}

__global__ __launch_bounds__(256) void k_fragWo(const float* __restrict__ Wo) {
    int idx = blockIdx.x * 256 + threadIdx.x;     // < 1048576
    int e = idx & 7, lane = (idx >> 3) & 31, s = (idx >> 8) & 3;
    int m = (idx >> 10) & 31, cta = (idx >> 15) & 7, l = idx >> 18;
    int g = lane >> 2, tg = lane & 3;
    int i = g + ((e >> 1) & 1) * 8;
    int kk = tg * 2 + (e & 1) + ((e >> 2) & 1) * 8;
    int col = m * 16 + i;
    int k = cta * 64 + s * 16 + kk;
    fWo[idx] = __float2half(Wo[(size_t)l * 262144 + (size_t)k * 512 + col]);
}

__global__ __launch_bounds__(256) void k_fragW1(const float* __restrict__ W1) {
    int idx = blockIdx.x * 256 + threadIdx.x;     // < 4194304
    int e = idx & 7, lane = (idx >> 3) & 31, s = (idx >> 8) & 31;
    int m = (idx >> 13) & 15, cta = (idx >> 17) & 7, l = idx >> 20;
    int g = lane >> 2, tg = lane & 3;
    int i = g + ((e >> 1) & 1) * 8;
    int kk = tg * 2 + (e & 1) + ((e >> 2) & 1) * 8;
    int col = cta * 256 + m * 16 + i;
    int k = s * 16 + kk;
    fW1[idx] = __float2half(W1[(size_t)l * 1048576 + (size_t)k * 2048 + col]);
}

__global__ __launch_bounds__(256) void k_fragW2(const float* __restrict__ W2) {
    int idx = blockIdx.x * 256 + threadIdx.x;     // < 4194304
    int e = idx & 7, lane = (idx >> 3) & 31, s = (idx >> 8) & 15;
    int m = (idx >> 12) & 31, cta = (idx >> 17) & 7, l = idx >> 20;
    int g = lane >> 2, tg = lane & 3;
    int i = g + ((e >> 1) & 1) * 8;
    int kk = tg * 2 + (e & 1) + ((e >> 2) & 1) * 8;
    int col = m * 16 + i;
    int k = cta * 256 + s * 16 + kk;
    fW2[idx] = __float2half(W2[(size_t)l * 1048576 + (size_t)k * 512 + col]);
}

__global__ __launch_bounds__(256) void k_fragOut(const float* __restrict__ motionr_W,
                                                 const float* __restrict__ motion_W) {
    int idx = blockIdx.x * 256 + threadIdx.x;     // < 393216
    int e = idx & 7, lane = (idx >> 3) & 31, s = (idx >> 8) & 31;
    int q = idx >> 13;
    int m = q % 6, cta = q / 6;
    int g = lane >> 2, tg = lane & 3;
    int i = g + ((e >> 1) & 1) * 8;
    int kk = tg * 2 + (e & 1) + ((e >> 2) & 1) * 8;
    int j = m * 16 + i;
    int k = s * 16 + kk;
    float v;
    if (j < 32) {
        v = motionr_W[(size_t)k * 256 + cta * 32 + j];
    } else {
        int col = cta * 64 + (j - 32);
        const float* mr = motionr_W + (size_t)k * 256;
        float acc = 0.f;
        for (int t = 0; t < 256; t++) acc += mr[t] * motion_W[(size_t)t * 512 + col];
        v = acc;
    }
    fOut[idx] = __float2half(v);
}

__global__ __launch_bounds__(256) void k_gb(const float* __restrict__ style,
                                            const float* __restrict__ W,
                                            const float* __restrict__ bias) {
    int idx = blockIdx.x * 256 + threadIdx.x;     // < 24576
    int j  = idx & 1023;
    int t  = idx >> 10;
    int b  = t & 1;
    int ls = t >> 1;
    float acc = bias[ls * 1024 + j];
    const float* w = W + (size_t)ls * 524288 + j;
    const float* x = style + b * 512;
    for (int e = 0; e < 512; e++) acc += x[e] * w[(size_t)e * 1024];
    g_gb[ls][b][j] = acc;
}

__global__ __launch_bounds__(256) void k_ca1(const float* __restrict__ content,
                                             const float* __restrict__ Wv,
                                             const float* __restrict__ bv) {
    int idx = blockIdx.x * 256 + threadIdx.x;     // < 131072
    int col = idx & 511;
    int l = idx >> 15;
    float acc = bv[l * 512 + col];
    const float* x = content + (size_t)((idx >> 9) & 63) * 512;
    const float* w = Wv + (size_t)l * 262144 + col;
    for (int e = 0; e < 512; e++) acc += x[e] * w[(size_t)e * 512];
    ((float*)g_Vt)[idx] = acc;
}

__global__ __launch_bounds__(256) void k_ca2(const float* __restrict__ Wo,
                                             const float* __restrict__ bo) {
    int idx = blockIdx.x * 256 + threadIdx.x;
    int col = idx & 511;
    int l = idx >> 15;
    float acc = bo[l * 512 + col];
    const float* x = ((const float*)g_Vt) + (size_t)(idx >> 9) * 512;
    const float* w = Wo + (size_t)l * 262144 + col;
    for (int e = 0; e < 512; e++) acc += x[e] * w[(size_t)e * 512];
    ((float*)g_CA)[idx] = acc;
}

__global__ __launch_bounds__(256) void k_tail(const float* __restrict__ motionr_b,
                                              const float* __restrict__ motion_W,
                                              const float* __restrict__ motion_b,
                                              const float* __restrict__ init_st) {
    int blk = blockIdx.x, tid = threadIdx.x;
    if (blk < 4) {
        int idx = blk * 256 + tid;
        int b = idx >> 9, col = idx & 511;
        const float* x = init_st + b * 256;
        float acc = 0.f;
        for (int e = 0; e < 256; e++) acc += x[e] * motion_W[(size_t)e * 512 + col];
        g_x0[b][col] = acc + motion_b[col] + g_ppe[0][col];
    } else {
        int col = (blk - 4) * 256 + tid;
        float acc = 0.f;
        for (int e = 0; e < 256; e++) acc += motionr_b[e] * motion_W[(size_t)e * 512 + col];
        g_bcomb[col] = acc + motion_b[col];
    }
}

// ======================= DECODE HELPERS ====================================

// single-batch SALN over arr[512] (thread t owns element t)
__device__ __forceinline__ void saln1(float* arr, const float* G,
                                      const float* add, float* red) {
    int tid = threadIdx.x;
    float a = arr[tid];
    float s = a, q = a * a;
#pragma unroll
    for (int o = 16; o; o >>= 1) {
        s += __shfl_xor_sync(0xffffffffu, s, o);
        q += __shfl_xor_sync(0xffffffffu, q, o);
    }
    int wid = tid >> 5;
    if ((tid & 31) == 0) { red[wid] = s; red[16 + wid] = q; }
    __syncthreads();
    if (tid == 0) {
        float S = 0.f, Q = 0.f;
#pragma unroll
        for (int k = 0; k < 16; k++) { S += red[k]; Q += red[16 + k]; }
        float mu = S * (1.f / 512.f);
        red[32] = mu;
        red[33] = rsqrtf(Q * (1.f / 512.f) - mu * mu + 1e-5f);
    }
    __syncthreads();
    float mu = red[32], rs = red[33];
    float o = (a - mu) * rs * G[tid] + G[512 + tid];
    if (add) o += add[tid];
    arr[tid] = o;        // own element; publish at caller's next sync
    __syncthreads();
}

__device__ __forceinline__ void mma16816(float& c0, float& c1, float& c2, float& c3,
                                         const uint4& a, unsigned b0, unsigned b1) {
    asm volatile("mma.sync.aligned.m16n8k16.row.col.f32.f16.f16.f32 "
                 "{%0,%1,%2,%3}, {%4,%5,%6,%7}, {%8,%9}, {%0,%1,%2,%3};"
                 : "+f"(c0), "+f"(c1), "+f"(c2), "+f"(c3)
                 : "r"(a.x), "r"(a.y), "r"(a.z), "r"(a.w), "r"(b0), "r"(b1));
}

// One 16-col tile over KSTEPS k16 steps, single batch (B col 0).
// Results at (lane&3)==0: c[0] = row g, c[2] = row g+8.
template <int KSTEPS>
__device__ __forceinline__ void mma_tile(const __half* __restrict__ frag,
                                         const __half* __restrict__ xh,
                                         float c[4]) {
    int lane = threadIdx.x & 31;
    int g = lane >> 2, tg = lane & 3;
    float d0 = 0, d1 = 0, d2 = 0, d3 = 0;
    float e0 = 0, e1 = 0, e2 = 0, e3 = 0;
    const uint4* fp = reinterpret_cast<const uint4*>(frag) + lane;
#pragma unroll
    for (int s = 0; s < KSTEPS; s++) {
        uint4 a = fp[s * 32];
        unsigned b0 = 0, b1 = 0;
        if (g == 0) {
            const __half* xb = xh + s * 16 + tg * 2;
            b0 = *reinterpret_cast<const unsigned*>(xb);
            b1 = *reinterpret_cast<const unsigned*>(xb + 8);
        }
        if (s & 1) mma16816(e0, e1, e2, e3, a, b0, b1);
        else       mma16816(d0, d1, d2, d3, a, b0, b1);
    }
    c[0] = d0 + e0; c[1] = d1 + e1; c[2] = d2 + e2; c[3] = d3 + e3;
}

// ======================= DECODE MEGAKERNEL =================================
// grid = 16 (2 clusters of 8); cluster = batch, CTA-in-cluster = head/slice
__global__ void __launch_bounds__(NTHR, 1) __cluster_dims__(NC, 1, 1) mega(
    const float* __restrict__ sa_bq, const float* __restrict__ sa_bk,
    const float* __restrict__ sa_bv, const float* __restrict__ sa_bo,
    const float* __restrict__ ff_b1, const float* __restrict__ ff_b2,
    const float* __restrict__ motionr_b,
    float* __restrict__ outp)
{
    extern __shared__ __align__(16) char dynsm[];
    Smem& sm = *reinterpret_cast<Smem*>(dynsm);
    const int bat = blockIdx.x >> 3;            // cluster id = batch
    const int cta = blockIdx.x & 7;             // rank in cluster = head/slice
    const int tid = threadIdx.x;
    const int w = tid >> 5, lane = tid & 31;
    const int g = lane >> 2, tg = lane & 3;

    for (int i = 0; i < NF; i++) {
        for (int l = 0; l < NL; l++) {
            // ==== stage A: (merge FF2 + saln3 | load x0) + QKV + attn + Wo partial
            if (l == 0) {
                sm.x[tid] = g_x0[bat][tid];
                __syncthreads();
            } else {
                float s0 = 0.f;
#pragma unroll
                for (int k = 0; k < NC; k++) s0 += g_part2[bat][k][tid];
                float y = s0 + ff_b2[(l - 1) * 512 + tid] + sm.x[tid];
                sm.x[tid] = y;
                __syncthreads();
                saln1(sm.x, g_gb[(l - 1) * 3 + 2][bat], 0, sm.red);
            }
            sm.xh[tid] = __float2half(sm.x[tid]);
            __syncthreads();
            // QKV: 12 warps, 1 tile each, K=512 (head = cta)
            if (w < 12) {
                float c[4];
                mma_tile<32>(fQKV + (((size_t)(l * NH + cta) * 12 + w) * 32) * 256,
                             sm.xh, c);
                if (tg == 0) {
#pragma unroll
                    for (int r = 0; r < 2; r++) {
                        int col192 = w * 16 + g + r * 8;
                        float v = c[r * 2];
                        int mtx = col192 >> 6, j = col192 & 63;
                        int colg = cta * 64 + j;
                        const float* bias = (mtx == 0 ? sa_bq : mtx == 1 ? sa_bk : sa_bv);
                        v += bias[l * 512 + colg];
                        if (mtx == 0)      sm.q[j] = v;
                        else if (mtx == 1) sm.K[l][i][j] = v;
                        else               sm.V[l][i][j] = v;
                    }
                }
            }
            __syncthreads();
            // scores + softmax (single batch, 1 warp)
            if (tid < 32) {
                int j = tid;
                float sc = -1e30f;
                if (j <= i) {
                    const float* kp = &sm.K[l][j][0];
                    float d = 0.f;
#pragma unroll 16
                    for (int e = 0; e < 64; e++) d += sm.q[e] * kp[e];
                    sc = d * 0.125f - exp2f(-(float)(cta + 1)) * (float)((i - j) / 30);
                }
                float mx = sc;
#pragma unroll
                for (int o = 16; o; o >>= 1) mx = fmaxf(mx, __shfl_xor_sync(0xffffffffu, mx, o));
                float ev = (j <= i) ? expf(sc - mx) : 0.f;
                float smm = ev;
#pragma unroll
                for (int o = 16; o; o >>= 1) smm += __shfl_xor_sync(0xffffffffu, smm, o);
                sm.att[j] = ev / smm;
            }
            __syncthreads();
            if (tid < 64) {
                float acc = 0.f;
                for (int j = 0; j <= i; j++)
                    acc += sm.att[j] * sm.V[l][j][tid];
                sm.o[tid] = acc;
                sm.oh[tid] = __float2half(acc);
            }
            __syncthreads();
            // Wo partial: 16 warps x 2 tiles, K=64
#pragma unroll
            for (int tt = 0; tt < 2; tt++) {
                int m = w * 2 + tt;
                float c[4];
                mma_tile<4>(fWo + (((size_t)(l * NC + cta) * 32 + m) * 4) * 256,
                            sm.oh, c);
                if (tg == 0) {
#pragma unroll
                    for (int r = 0; r < 2; r++) {
                        int col = m * 16 + g + r * 8;
                        g_part[bat][cta][col] = c[r * 2];
                    }
                }
            }
            csync();

            // ==== stage B: merge attn + saln1+CA+saln2 + FF1 + FF2 partial ====
            {
                float s0 = 0.f;
#pragma unroll
                for (int k = 0; k < NC; k++) s0 += g_part[bat][k][tid];
                float y = s0 + sa_bo[l * 512 + tid] + sm.x[tid];
                sm.x[tid] = y;
                __syncthreads();
                saln1(sm.x, g_gb[l * 3 + 0][bat], &g_CA[l][bat][i][0], sm.red);
                saln1(sm.x, g_gb[l * 3 + 1][bat], 0, sm.red);
                sm.xh[tid] = __float2half(sm.x[tid]);
                __syncthreads();
                // FF1: 16 warps x 1 tile, K=512 -> hh (fp16, local)
                {
                    float c[4];
                    mma_tile<32>(fW1 + (((size_t)(l * NC + cta) * 16 + w) * 32) * 256,
                                 sm.xh, c);
                    if (tg == 0) {
#pragma unroll
                        for (int r = 0; r < 2; r++) {
                            int col = w * 16 + g + r * 8;      // 0..255 local
                            float b1f = ff_b1[l * 2048 + cta * 256 + col];
                            sm.hh[col] = __float2half(fmaxf(c[r * 2] + b1f, 0.f));
                        }
                    }
                }
                __syncthreads();
                // FF2 partial: 16 warps x 2 tiles, K=256
#pragma unroll
                for (int tt = 0; tt < 2; tt++) {
                    int m = w * 2 + tt;
                    float c[4];
                    mma_tile<16>(fW2 + (((size_t)(l * NC + cta) * 32 + m) * 16) * 256,
                                 sm.hh, c);
                    if (tg == 0) {
#pragma unroll
                        for (int r = 0; r < 2; r++) {
                            int col = m * 16 + g + r * 8;
                            g_part2[bat][cta][col] = c[r * 2];
                        }
                    }
                }
            }
            csync();
        } // layers

        // ==== stage OUT: merge FF2 + saln3 -> out row + next embedding ====
        {
            float s0 = 0.f;
#pragma unroll
            for (int k = 0; k < NC; k++) s0 += g_part2[bat][k][tid];
            float y = s0 + ff_b2[3 * 512 + tid] + sm.x[tid];
            sm.x[tid] = y;
            __syncthreads();
            saln1(sm.x, g_gb[11][bat], 0, sm.red);
            sm.xh[tid] = __float2half(sm.x[tid]);
            __syncthreads();
            if (w < 6) {
                float c[4];
                mma_tile<32>(fOut + (((size_t)(cta * 6 + w)) * 32) * 256,
                             sm.xh, c);
                if (tg == 0) {
#pragma unroll
                    for (int r = 0; r < 2; r++) {
                        int j = w * 16 + g + r * 8;
                        float v = c[r * 2];
                        if (j < 32) {
                            int col = cta * 32 + j;
                            outp[(size_t)bat * 8192 + (size_t)i * 256 + col] =
                                v + motionr_b[col];
                        } else if (i < NF - 1) {
                            int col = cta * 64 + (j - 32);
                            g_x0[bat][col] = v + g_bcomb[col] + g_ppe[i + 1][col];
                        }
                    }
                }
            }
        }
        csync();
    } // steps
}

// ---------------------------------------------------------------------------
extern "C" void kernel_launch(void* const* d_in, const int* in_sizes, int n_in,
                              void* d_out, int out_size) {
    const float* content   = (const float*)d_in[0];
    const float* style     = (const float*)d_in[1];
    const float* init_st   = (const float*)d_in[2];
    const float* motion_W  = (const float*)d_in[3];
    const float* motion_b  = (const float*)d_in[4];
    const float* motionr_W = (const float*)d_in[5];
    const float* motionr_b = (const float*)d_in[6];
    const float* sa_Wq = (const float*)d_in[7];
    const float* sa_bq = (const float*)d_in[8];
    const float* sa_Wk = (const float*)d_in[9];
    const float* sa_bk = (const float*)d_in[10];
    const float* sa_Wv = (const float*)d_in[11];
    const float* sa_bv = (const float*)d_in[12];
    const float* sa_Wo = (const float*)d_in[13];
    const float* sa_bo = (const float*)d_in[14];
    // 15-18 (ca_Wq/bq/Wk/bk) unused: one-hot cross-attn softmax
    const float* ca_Wv = (const float*)d_in[19];
    const float* ca_bv = (const float*)d_in[20];
    const float* ca_Wo = (const float*)d_in[21];
    const float* ca_bo = (const float*)d_in[22];
    const float* ff_W1 = (const float*)d_in[23];
    const float* ff_b1 = (const float*)d_in[24];
    const float* ff_W2 = (const float*)d_in[25];
    const float* ff_b2 = (const float*)d_in[26];
    const float* saln_W = (const float*)d_in[27];
    const float* saln_b = (const float*)d_in[28];
    float* outp = (float*)d_out;

    k_ppe<<<(NF * ND) / 256, 256>>>();
    k_fragQKV<<<3145728 / 256, 256>>>(sa_Wq, sa_Wk, sa_Wv);
    k_fragWo<<<1048576 / 256, 256>>>(sa_Wo);
    k_fragW1<<<4194304 / 256, 256>>>(ff_W1);
    k_fragW2<<<4194304 / 256, 256>>>(ff_W2);
    k_fragOut<<<393216 / 256, 256>>>(motionr_W, motion_W);
    k_gb<<<96, 256>>>(style, saln_W, saln_b);
    k_ca1<<<512, 256>>>(content, ca_Wv, ca_bv);
    k_ca2<<<512, 256>>>(ca_Wo, ca_bo);
    k_tail<<<6, 256>>>(motionr_b, motion_W, motion_b, init_st);

    cudaFuncSetAttribute(mega, cudaFuncAttributeMaxDynamicSharedMemorySize,
                         (int)SMEM_BYTES);
    mega<<<NB * NC, NTHR, SMEM_BYTES>>>(sa_bq, sa_bk, sa_bv, sa_bo,
                                        ff_b1, ff_b2, motionr_b, outp);
    (void)in_sizes; (void)n_in; (void)out_size;
}

// round 17
// speedup vs baseline: 2.0948x; 1.0458x over previous
#include <cuda_runtime.h>
#include <cuda_fp16.h>
#include <math.h>

#define NTHR 512
#define NC 8            // cluster size (portable max); 2 clusters = 2 batches

#define NB 2
#define NF 32
#define ND 512
#define NH 8
#define NHD 64
#define NFF 2048
#define NL 4
#define NM 256

// ---------------- persistent device state (no allocs) ----------------
__device__ __align__(16) float g_Vt[NL][NB][NF][ND];
__device__ __align__(16) float g_CA[NL][NB][NF][ND];
__device__ __align__(16) float g_gb[NL * 3][NB][2 * ND];
__device__ __align__(16) float g_ppe[NF][ND];
__device__ __align__(16) float g_x0[NB][ND];
__device__ __align__(16) float g_part [NB][NC][ND];   // attn o@Wo partials
__device__ __align__(16) float g_part2[NB][NC][ND];   // FF2 partials
__device__ __align__(16) float g_bcomb[ND];

// fragment-ordered fp16 weights (A-fragments for mma.m16n8k16, row.col)
__device__ __align__(16) __half fQKV[NL * NH * 12 * 32 * 256];  // 192 cols, K=512
__device__ __align__(16) __half fWo [NL * NC * 32 * 4  * 256];  // 512 cols, K=64
__device__ __align__(16) __half fW1 [NL * NC * 16 * 32 * 256];  // 256 cols, K=512
__device__ __align__(16) __half fW2 [NL * NC * 32 * 16 * 256];  // 512 cols, K=256
__device__ __align__(16) __half fOut[NC * 6 * 32 * 256];        // 96 cols, K=512

struct __align__(16) Smem {
    float x[512];             // single-batch activation (persists across csync)
    float q[64];
    float att[32];
    float red[96];            // two 48-float saln regions
    __align__(16) __half xh[512];
    __align__(16) __half hh[256];
    __align__(16) __half oh[64];
    float K[NL][NF][65];
    float V[NL][NF][65];
};
#define SMEM_BYTES sizeof(Smem)

#define CARRIVE() asm volatile("barrier.cluster.arrive.aligned;" ::: "memory")
#define CWAIT()   asm volatile("barrier.cluster.wait.aligned;" ::: "memory")

// Fragment element mapping (shared by prep writers and consumer):
//   lane: g = lane>>2, tg = lane&3
//   e (0..7): row i = g + ((e>>1)&1)*8 ; k kk = tg*2 + (e&1) + ((e>>2)&1)*8

// ======================= PREP KERNELS (unchanged from R16) =================

__global__ __launch_bounds__(256) void k_ppe() {
    int idx = blockIdx.x * 256 + threadIdx.x;
    int f = idx >> 9, d = idx & 511;
    float divv = expf((float)(d & ~1) * (-9.210340371976184f / 512.0f));
    float a = (float)(f % 30) * divv;
    g_ppe[f][d] = (d & 1) ? cosf(a) : sinf(a);
}

__global__ __launch_bounds__(256) void k_fragQKV(const float* __restrict__ Wq,
                                                 const float* __restrict__ Wk,
                                                 const float* __restrict__ Wv) {
    int idx = blockIdx.x * 256 + threadIdx.x;
    int e = idx & 7, lane = (idx >> 3) & 31, s = (idx >> 8) & 31;
    int q = idx >> 13;
    int m = q % 12, p = q / 12;
    int h = p & 7, l = p >> 3;
    int g = lane >> 2, tg = lane & 3;
    int i = g + ((e >> 1) & 1) * 8;
    int kk = tg * 2 + (e & 1) + ((e >> 2) & 1) * 8;
    int col192 = m * 16 + i;
    int mtx = col192 >> 6;
    int cw = h * 64 + (col192 & 63);
    int k = s * 16 + kk;
    const float* src = (mtx == 0 ? Wq : mtx == 1 ? Wk : Wv);
    fQKV[idx] = __float2half(src[(size_t)l * 262144 + (size_t)k * 512 + cw]);
}

__global__ __launch_bounds__(256) void k_fragWo(const float* __restrict__ Wo) {
    int idx = blockIdx.x * 256 + threadIdx.x;
    int e = idx & 7, lane = (idx >> 3) & 31, s = (idx >> 8) & 3;
    int m = (idx >> 10) & 31, cta = (idx >> 15) & 7, l = idx >> 18;
    int g = lane >> 2, tg = lane & 3;
    int i = g + ((e >> 1) & 1) * 8;
    int kk = tg * 2 + (e & 1) + ((e >> 2) & 1) * 8;
    int col = m * 16 + i;
    int k = cta * 64 + s * 16 + kk;
    fWo[idx] = __float2half(Wo[(size_t)l * 262144 + (size_t)k * 512 + col]);
}

__global__ __launch_bounds__(256) void k_fragW1(const float* __restrict__ W1) {
    int idx = blockIdx.x * 256 + threadIdx.x;
    int e = idx & 7, lane = (idx >> 3) & 31, s = (idx >> 8) & 31;
    int m = (idx >> 13) & 15, cta = (idx >> 17) & 7, l = idx >> 20;
    int g = lane >> 2, tg = lane & 3;
    int i = g + ((e >> 1) & 1) * 8;
    int kk = tg * 2 + (e & 1) + ((e >> 2) & 1) * 8;
    int col = cta * 256 + m * 16 + i;
    int k = s * 16 + kk;
    fW1[idx] = __float2half(W1[(size_t)l * 1048576 + (size_t)k * 2048 + col]);
}

__global__ __launch_bounds__(256) void k_fragW2(const float* __restrict__ W2) {
    int idx = blockIdx.x * 256 + threadIdx.x;
    int e = idx & 7, lane = (idx >> 3) & 31, s = (idx >> 8) & 15;
    int m = (idx >> 12) & 31, cta = (idx >> 17) & 7, l = idx >> 20;
    int g = lane >> 2, tg = lane & 3;
    int i = g + ((e >> 1) & 1) * 8;
    int kk = tg * 2 + (e & 1) + ((e >> 2) & 1) * 8;
    int col = m * 16 + i;
    int k = cta * 256 + s * 16 + kk;
    fW2[idx] = __float2half(W2[(size_t)l * 1048576 + (size_t)k * 512 + col]);
}

__global__ __launch_bounds__(256) void k_fragOut(const float* __restrict__ motionr_W,
                                                 const float* __restrict__ motion_W) {
    int idx = blockIdx.x * 256 + threadIdx.x;
    int e = idx & 7, lane = (idx >> 3) & 31, s = (idx >> 8) & 31;
    int q = idx >> 13;
    int m = q % 6, cta = q / 6;
    int g = lane >> 2, tg = lane & 3;
    int i = g + ((e >> 1) & 1) * 8;
    int kk = tg * 2 + (e & 1) + ((e >> 2) & 1) * 8;
    int j = m * 16 + i;
    int k = s * 16 + kk;
    float v;
    if (j < 32) {
        v = motionr_W[(size_t)k * 256 + cta * 32 + j];
    } else {
        int col = cta * 64 + (j - 32);
        const float* mr = motionr_W + (size_t)k * 256;
        float acc = 0.f;
        for (int t = 0; t < 256; t++) acc += mr[t] * motion_W[(size_t)t * 512 + col];
        v = acc;
    }
    fOut[idx] = __float2half(v);
}

__global__ __launch_bounds__(256) void k_gb(const float* __restrict__ style,
                                            const float* __restrict__ W,
                                            const float* __restrict__ bias) {
    int idx = blockIdx.x * 256 + threadIdx.x;
    int j  = idx & 1023;
    int t  = idx >> 10;
    int b  = t & 1;
    int ls = t >> 1;
    float acc = bias[ls * 1024 + j];
    const float* w = W + (size_t)ls * 524288 + j;
    const float* x = style + b * 512;
    for (int e = 0; e < 512; e++) acc += x[e] * w[(size_t)e * 1024];
    g_gb[ls][b][j] = acc;
}

__global__ __launch_bounds__(256) void k_ca1(const float* __restrict__ content,
                                             const float* __restrict__ Wv,
                                             const float* __restrict__ bv) {
    int idx = blockIdx.x * 256 + threadIdx.x;
    int col = idx & 511;
    int l = idx >> 15;
    float acc = bv[l * 512 + col];
    const float* x = content + (size_t)((idx >> 9) & 63) * 512;
    const float* w = Wv + (size_t)l * 262144 + col;
    for (int e = 0; e < 512; e++) acc += x[e] * w[(size_t)e * 512];
    ((float*)g_Vt)[idx] = acc;
}

__global__ __launch_bounds__(256) void k_ca2(const float* __restrict__ Wo,
                                             const float* __restrict__ bo) {
    int idx = blockIdx.x * 256 + threadIdx.x;
    int col = idx & 511;
    int l = idx >> 15;
    float acc = bo[l * 512 + col];
    const float* x = ((const float*)g_Vt) + (size_t)(idx >> 9) * 512;
    const float* w = Wo + (size_t)l * 262144 + col;
    for (int e = 0; e < 512; e++) acc += x[e] * w[(size_t)e * 512];
    ((float*)g_CA)[idx] = acc;
}

__global__ __launch_bounds__(256) void k_tail(const float* __restrict__ motionr_b,
                                              const float* __restrict__ motion_W,
                                              const float* __restrict__ motion_b,
                                              const float* __restrict__ init_st) {
    int blk = blockIdx.x, tid = threadIdx.x;
    if (blk < 4) {
        int idx = blk * 256 + tid;
        int b = idx >> 9, col = idx & 511;
        const float* x = init_st + b * 256;
        float acc = 0.f;
        for (int e = 0; e < 256; e++) acc += x[e] * motion_W[(size_t)e * 512 + col];
        g_x0[b][col] = acc + motion_b[col] + g_ppe[0][col];
    } else {
        int col = (blk - 4) * 256 + tid;
        float acc = 0.f;
        for (int e = 0; e < 256; e++) acc += motionr_b[e] * motion_W[(size_t)e * 512 + col];
        g_bcomb[col] = acc + motion_b[col];
    }
}

// ======================= DECODE HELPERS ====================================

// register-resident SALN: ONE syncthreads, value returned in register.
// red = fresh 48-float region per call (alternate regions between calls).
__device__ __forceinline__ float saln_reg(float a, const float* __restrict__ G,
                                          const float* __restrict__ add,
                                          float* __restrict__ red) {
    int tid = threadIdx.x;
    float s = a, q = a * a;
#pragma unroll
    for (int o = 16; o; o >>= 1) {
        s += __shfl_xor_sync(0xffffffffu, s, o);
        q += __shfl_xor_sync(0xffffffffu, q, o);
    }
    if ((tid & 31) == 0) { red[tid >> 5] = s; red[16 + (tid >> 5)] = q; }
    __syncthreads();
    float S = 0.f, Q = 0.f;
#pragma unroll
    for (int k = 0; k < 16; k++) { S += red[k]; Q += red[16 + k]; }
    float mu = S * (1.f / 512.f);
    float rs = rsqrtf(Q * (1.f / 512.f) - mu * mu + 1e-5f);
    float o = (a - mu) * rs * G[tid] + G[512 + tid];
    if (add) o += add[tid];
    return o;
}

__device__ __forceinline__ void mma16816(float& c0, float& c1, float& c2, float& c3,
                                         const uint4& a, unsigned b0, unsigned b1) {
    asm volatile("mma.sync.aligned.m16n8k16.row.col.f32.f16.f16.f32 "
                 "{%0,%1,%2,%3}, {%4,%5,%6,%7}, {%8,%9}, {%0,%1,%2,%3};"
                 : "+f"(c0), "+f"(c1), "+f"(c2), "+f"(c3)
                 : "r"(a.x), "r"(a.y), "r"(a.z), "r"(a.w), "r"(b0), "r"(b1));
}

template <int PRE>
__device__ __forceinline__ void pre_frags(const __half* __restrict__ frag,
                                          uint4* pre) {
    const uint4* fp = reinterpret_cast<const uint4*>(frag) + (threadIdx.x & 31);
#pragma unroll
    for (int s = 0; s < PRE; s++) pre[s] = fp[s * 32];
}

// single-batch mma tile with optional preloaded fragment prefix
template <int KSTEPS, int PRE>
__device__ __forceinline__ void mma_tile_p(const uint4* pre,
                                           const __half* __restrict__ frag,
                                           const __half* __restrict__ xh,
                                           float c[4]) {
    int lane = threadIdx.x & 31;
    int g = lane >> 2, tg = lane & 3;
    float d0 = 0, d1 = 0, d2 = 0, d3 = 0;
    float e0 = 0, e1 = 0, e2 = 0, e3 = 0;
    const uint4* fp = reinterpret_cast<const uint4*>(frag) + lane;
#pragma unroll
    for (int s = 0; s < KSTEPS; s++) {
        uint4 a = (s < PRE) ? pre[s] : fp[s * 32];
        unsigned b0 = 0, b1 = 0;
        if (g == 0) {
            const __half* xb = xh + s * 16 + tg * 2;
            b0 = *reinterpret_cast<const unsigned*>(xb);
            b1 = *reinterpret_cast<const unsigned*>(xb + 8);
        }
        if (s & 1) mma16816(e0, e1, e2, e3, a, b0, b1);
        else       mma16816(d0, d1, d2, d3, a, b0, b1);
    }
    c[0] = d0 + e0; c[1] = d1 + e1; c[2] = d2 + e2; c[3] = d3 + e3;
}

// ======================= DECODE MEGAKERNEL =================================
// grid = 16 (2 clusters of 8); cluster = batch, CTA-in-cluster = head/slice
__global__ void __launch_bounds__(NTHR, 1) __cluster_dims__(NC, 1, 1) mega(
    const float* __restrict__ sa_bq, const float* __restrict__ sa_bk,
    const float* __restrict__ sa_bv, const float* __restrict__ sa_bo,
    const float* __restrict__ ff_b1, const float* __restrict__ ff_b2,
    const float* __restrict__ motionr_b,
    float* __restrict__ outp)
{
    extern __shared__ __align__(16) char dynsm[];
    Smem& sm = *reinterpret_cast<Smem*>(dynsm);
    const int bat = blockIdx.x >> 3;
    const int cta = blockIdx.x & 7;
    const int tid = threadIdx.x;
    const int w = tid >> 5, lane = tid & 31;
    const int g = lane >> 2, tg = lane & 3;

    uint4 qkvPre[4], ff1Pre[4], outPre[4];
    if (w < 12)
        pre_frags<4>(fQKV + (((size_t)(0 * NH + cta) * 12 + w) * 32) * 256, qkvPre);

    for (int i = 0; i < NF; i++) {
        for (int l = 0; l < NL; l++) {
            // ==== stage A: x prep + QKV + attn + Wo partial ====
            float y;
            if (l == 0) {
                y = g_x0[bat][tid];
            } else {
                float s0 = 0.f;
#pragma unroll
                for (int k = 0; k < NC; k++) s0 += g_part2[bat][k][tid];
                y = s0 + ff_b2[(l - 1) * 512 + tid] + sm.x[tid];
                y = saln_reg(y, g_gb[(l - 1) * 3 + 2][bat], 0, sm.red);
            }
            sm.x[tid] = y;
            sm.xh[tid] = __float2half(y);
            __syncthreads();
            // QKV: 12 warps, K=512, with prefix preloaded across the barrier
            if (w < 12) {
                float c[4];
                mma_tile_p<32, 4>(qkvPre,
                                  fQKV + (((size_t)(l * NH + cta) * 12 + w) * 32) * 256,
                                  sm.xh, c);
                if (tg == 0) {
#pragma unroll
                    for (int r = 0; r < 2; r++) {
                        int col192 = w * 16 + g + r * 8;
                        float v = c[r * 2];
                        int mtx = col192 >> 6, j = col192 & 63;
                        int colg = cta * 64 + j;
                        const float* bias = (mtx == 0 ? sa_bq : mtx == 1 ? sa_bk : sa_bv);
                        v += bias[l * 512 + colg];
                        if (mtx == 0)      sm.q[j] = v;
                        else if (mtx == 1) sm.K[l][i][j] = v;
                        else               sm.V[l][i][j] = v;
                    }
                }
            }
            __syncthreads();
            // scores + softmax (1 warp)
            if (tid < 32) {
                int j = tid;
                float sc = -1e30f;
                if (j <= i) {
                    const float* kp = &sm.K[l][j][0];
                    float d = 0.f;
#pragma unroll 16
                    for (int e = 0; e < 64; e++) d += sm.q[e] * kp[e];
                    sc = d * 0.125f - exp2f(-(float)(cta + 1)) * (float)((i - j) / 30);
                }
                float mx = sc;
#pragma unroll
                for (int o = 16; o; o >>= 1) mx = fmaxf(mx, __shfl_xor_sync(0xffffffffu, mx, o));
                float ev = (j <= i) ? expf(sc - mx) : 0.f;
                float smm = ev;
#pragma unroll
                for (int o = 16; o; o >>= 1) smm += __shfl_xor_sync(0xffffffffu, smm, o);
                sm.att[j] = ev / smm;
            }
            __syncthreads();
            if (tid < 64) {
                float acc = 0.f;
                for (int j = 0; j <= i; j++)
                    acc += sm.att[j] * sm.V[l][j][tid];
                sm.oh[tid] = __float2half(acc);
            }
            __syncthreads();
            // Wo partial: 16 warps x 2 tiles, K=64
#pragma unroll
            for (int tt = 0; tt < 2; tt++) {
                int m = w * 2 + tt;
                float c[4];
                mma_tile_p<4, 0>(0, fWo + (((size_t)(l * NC + cta) * 32 + m) * 4) * 256,
                                 sm.oh, c);
                if (tg == 0) {
#pragma unroll
                    for (int r = 0; r < 2; r++) {
                        int col = m * 16 + g + r * 8;
                        g_part[bat][cta][col] = c[r * 2];
                    }
                }
            }
            CARRIVE();
            pre_frags<4>(fW1 + (((size_t)(l * NC + cta) * 16 + w) * 32) * 256, ff1Pre);
            CWAIT();

            // ==== stage B: merge attn + saln1+CA+saln2 + FF1 + FF2 partial ====
            {
                float s0 = 0.f;
#pragma unroll
                for (int k = 0; k < NC; k++) s0 += g_part[bat][k][tid];
                float yy = s0 + sa_bo[l * 512 + tid] + sm.x[tid];
                yy = saln_reg(yy, g_gb[l * 3 + 0][bat], &g_CA[l][bat][i][0], sm.red);
                yy = saln_reg(yy, g_gb[l * 3 + 1][bat], 0, sm.red + 48);
                sm.x[tid] = yy;
                sm.xh[tid] = __float2half(yy);
                __syncthreads();
                // FF1: 16 warps x 1 tile, K=512, prefix preloaded
                {
                    float c[4];
                    mma_tile_p<32, 4>(ff1Pre,
                                      fW1 + (((size_t)(l * NC + cta) * 16 + w) * 32) * 256,
                                      sm.xh, c);
                    if (tg == 0) {
#pragma unroll
                        for (int r = 0; r < 2; r++) {
                            int col = w * 16 + g + r * 8;
                            float b1f = ff_b1[l * 2048 + cta * 256 + col];
                            sm.hh[col] = __float2half(fmaxf(c[r * 2] + b1f, 0.f));
                        }
                    }
                }
                __syncthreads();
                // FF2 partial: 16 warps x 2 tiles, K=256
#pragma unroll
                for (int tt = 0; tt < 2; tt++) {
                    int m = w * 2 + tt;
                    float c[4];
                    mma_tile_p<16, 0>(0, fW2 + (((size_t)(l * NC + cta) * 32 + m) * 16) * 256,
                                      sm.hh, c);
                    if (tg == 0) {
#pragma unroll
                        for (int r = 0; r < 2; r++) {
                            int col = m * 16 + g + r * 8;
                            g_part2[bat][cta][col] = c[r * 2];
                        }
                    }
                }
            }
            CARRIVE();
            if (l < NL - 1) {
                if (w < 12)
                    pre_frags<4>(fQKV + (((size_t)((l + 1) * NH + cta) * 12 + w) * 32) * 256,
                                 qkvPre);
            } else {
                if (w < 6)
                    pre_frags<4>(fOut + (((size_t)(cta * 6 + w)) * 32) * 256, outPre);
            }
            CWAIT();
        } // layers

        // ==== stage OUT: merge FF2 + saln3 -> out row + next embedding ====
        {
            float s0 = 0.f;
#pragma unroll
            for (int k = 0; k < NC; k++) s0 += g_part2[bat][k][tid];
            float yy = s0 + ff_b2[3 * 512 + tid] + sm.x[tid];
            yy = saln_reg(yy, g_gb[11][bat], 0, sm.red);
            sm.xh[tid] = __float2half(yy);
            __syncthreads();
            if (w < 6) {
                float c[4];
                mma_tile_p<32, 4>(outPre,
                                  fOut + (((size_t)(cta * 6 + w)) * 32) * 256,
                                  sm.xh, c);
                if (tg == 0) {
#pragma unroll
                    for (int r = 0; r < 2; r++) {
                        int j = w * 16 + g + r * 8;
                        float v = c[r * 2];
                        if (j < 32) {
                            int col = cta * 32 + j;
                            outp[(size_t)bat * 8192 + (size_t)i * 256 + col] =
                                v + motionr_b[col];
                        } else if (i < NF - 1) {
                            int col = cta * 64 + (j - 32);
                            g_x0[bat][col] = v + g_bcomb[col] + g_ppe[i + 1][col];
                        }
                    }
                }
            }
        }
        CARRIVE();
        if (w < 12)
            pre_frags<4>(fQKV + (((size_t)(0 * NH + cta) * 12 + w) * 32) * 256, qkvPre);
        CWAIT();
    } // steps
}

// ---------------------------------------------------------------------------
extern "C" void kernel_launch(void* const* d_in, const int* in_sizes, int n_in,
                              void* d_out, int out_size) {
    const float* content   = (const float*)d_in[0];
    const float* style     = (const float*)d_in[1];
    const float* init_st   = (const float*)d_in[2];
    const float* motion_W  = (const float*)d_in[3];
    const float* motion_b  = (const float*)d_in[4];
    const float* motionr_W = (const float*)d_in[5];
    const float* motionr_b = (const float*)d_in[6];
    const float* sa_Wq = (const float*)d_in[7];
    const float* sa_bq = (const float*)d_in[8];
    const float* sa_Wk = (const float*)d_in[9];
    const float* sa_bk = (const float*)d_in[10];
    const float* sa_Wv = (const float*)d_in[11];
    const float* sa_bv = (const float*)d_in[12];
    const float* sa_Wo = (const float*)d_in[13];
    const float* sa_bo = (const float*)d_in[14];
    // 15-18 (ca_Wq/bq/Wk/bk) unused: one-hot cross-attn softmax
    const float* ca_Wv = (const float*)d_in[19];
    const float* ca_bv = (const float*)d_in[20];
    const float* ca_Wo = (const float*)d_in[21];
    const float* ca_bo = (const float*)d_in[22];
    const float* ff_W1 = (const float*)d_in[23];
    const float* ff_b1 = (const float*)d_in[24];
    const float* ff_W2 = (const float*)d_in[25];
    const float* ff_b2 = (const float*)d_in[26];
    const float* saln_W = (const float*)d_in[27];
    const float* saln_b = (const float*)d_in[28];
    float* outp = (float*)d_out;

    k_ppe<<<(NF * ND) / 256, 256>>>();
    k_fragQKV<<<3145728 / 256, 256>>>(sa_Wq, sa_Wk, sa_Wv);
    k_fragWo<<<1048576 / 256, 256>>>(sa_Wo);
    k_fragW1<<<4194304 / 256, 256>>>(ff_W1);
    k_fragW2<<<4194304 / 256, 256>>>(ff_W2);
    k_fragOut<<<393216 / 256, 256>>>(motionr_W, motion_W);
    k_gb<<<96, 256>>>(style, saln_W, saln_b);
    k_ca1<<<512, 256>>>(content, ca_Wv, ca_bv);
    k_ca2<<<512, 256>>>(ca_Wo, ca_bo);
    k_tail<<<6, 256>>>(motionr_b, motion_W, motion_b, init_st);

    cudaFuncSetAttribute(mega, cudaFuncAttributeMaxDynamicSharedMemorySize,
                         (int)SMEM_BYTES);
    mega<<<NB * NC, NTHR, SMEM_BYTES>>>(sa_bq, sa_bk, sa_bv, sa_bo,
                                        ff_b1, ff_b2, motionr_b, outp);
    (void)in_sizes; (void)n_in; (void)out_size;
}